// round 13
// baseline (speedup 1.0000x reference)
#include <cuda_runtime.h>
#include <cuda_bf16.h>
#include <cstdint>
#include <cstddef>

#define M_MSG 131072
#define NNODE 65536
#define HID   256
#define DEPTH 6
#define NTREE 2048
#define GRID_P 148

#if defined(__CUDA_ARCH_FEAT_SM103_ALL) || defined(__CUDA_ARCH_FEAT_SM100_ALL) || \
    defined(__CUDA_ARCH_FEAT_SM101_ALL) || defined(__CUDA_ARCH_FEAT_SM110_ALL)
#define TC_OK 1
#else
#define TC_OK 0
#endif

// ---------------- static device scratch ------------------------------------
// Per-message record: [0:256) h_hi | [256:512) h_lo | [512:768) U   (bf16)
__device__ __nv_bfloat16 g_rec[(size_t)M_MSG * 768];
// GEMM A operands as bf16 hi/lo planes
__device__ __nv_bfloat16 g_shh[(size_t)M_MSG * 256], g_shl[(size_t)M_MSG * 256]; // sum_h
__device__ __nv_bfloat16 g_sgh[(size_t)M_MSG * 256], g_sgl[(size_t)M_MSG * 256]; // sum_gh
__device__ __nv_bfloat16 g_mnh[(size_t)NNODE * 256], g_mnl[(size_t)NNODE * 256]; // mess_nei
__device__ float g_nv[(size_t)NNODE * 256];           // node_vec
__device__ float g_EX[780 * 768];                     // emb@[Wzx|Whx|Wr]+biases
__device__ float g_EO[780 * 256];                     // emb@Ow1+Ob
__device__ int   g_mx[M_MSG];                         // fnode[fmess[m]]
// bf16 hi/lo split weights, [n][k] layout (B operand = W^T), all 256x256
__device__ __nv_bfloat16 g_BUh[256 * 256], g_BUl[256 * 256];  // Ur^T
__device__ __nv_bfloat16 g_BZh[256 * 256], g_BZl[256 * 256];  // Wzh^T
__device__ __nv_bfloat16 g_BHh[256 * 256], g_BHl[256 * 256];  // Whh^T
__device__ __nv_bfloat16 g_BOh[256 * 256], g_BOl[256 * 256];  // Ow2^T

// ---------------- bf16 helpers ----------------------------------------------
__device__ __forceinline__ float bf_lo16(uint32_t u) { return __uint_as_float(u << 16); }
__device__ __forceinline__ float bf_hi16(uint32_t u) { return __uint_as_float(u & 0xFFFF0000u); }
__device__ __forceinline__ uint32_t bf2pk(float a, float b) {
    return (uint32_t)__bfloat16_as_ushort(__float2bfloat16(a))
         | ((uint32_t)__bfloat16_as_ushort(__float2bfloat16(b)) << 16);
}
__device__ __forceinline__ float lo_of(float v) {
    return v - __bfloat162float(__float2bfloat16(v));
}
__device__ __forceinline__ float sgm(float x) { return 1.0f / (1.0f + __expf(-x)); }

// ---------------- PTX helpers ------------------------------------------------
__device__ __forceinline__ uint32_t su32(const void* p) {
    uint32_t a;
    asm("{ .reg .u64 t; cvta.to.shared.u64 t, %1; cvt.u32.u64 %0, t; }"
        : "=r"(a) : "l"(p));
    return a;
}
#if TC_OK
__device__ __forceinline__ bool elect1() {
    uint32_t p;
    asm volatile("{\n\t.reg .pred p;\n\telect.sync _|p, 0xFFFFFFFF;\n\t"
                 "selp.b32 %0, 1, 0, p;\n\t}" : "=r"(p));
    return p != 0;
}
__device__ __forceinline__ void mbar_init(uint32_t a, uint32_t cnt) {
    asm volatile("mbarrier.init.shared.b64 [%0], %1;" :: "r"(a), "r"(cnt) : "memory");
}
__device__ __forceinline__ void mbar_wait(uint32_t a, int par) {
    asm volatile(
        "{\n\t.reg .pred P;\n"
        "W%=:\n\t"
        "mbarrier.try_wait.parity.acquire.cta.shared::cta.b64 P, [%0], %1, 0x989680;\n\t"
        "@P bra.uni D%=;\n\t"
        "bra.uni W%=;\n"
        "D%=:\n\t}" :: "r"(a), "r"(par) : "memory");
}
__device__ __forceinline__ void tc_alloc(uint32_t smem_res, uint32_t ncols) {
    asm volatile("tcgen05.alloc.cta_group::1.sync.aligned.shared::cta.b32 [%0], %1;"
                 :: "r"(smem_res), "r"(ncols) : "memory");
}
__device__ __forceinline__ void tc_dealloc(uint32_t tmem, uint32_t ncols) {
    asm volatile("tcgen05.dealloc.cta_group::1.sync.aligned.b32 %0, %1;"
                 :: "r"(tmem), "r"(ncols));
}
__device__ __forceinline__ void tc_commit(uint32_t mbar) {
    asm volatile("tcgen05.commit.cta_group::1.mbarrier::arrive::one.shared::cluster.b64 [%0];"
                 :: "r"(mbar) : "memory");
}
__device__ __forceinline__ void mma_f16_ss(uint32_t d, uint64_t ad, uint64_t bd,
                                           uint32_t idesc, bool acc) {
    uint32_t en = acc ? 1u : 0u;
    asm volatile(
        "{\n\t.reg .pred p;\n\tsetp.ne.u32 p, %5, 0;\n\t"
        "tcgen05.mma.cta_group::1.kind::f16 [%0], %1, %2, %3, {%4, %4, %4, %4}, p;\n\t}"
        :: "r"(d), "l"(ad), "l"(bd), "r"(idesc), "r"(0u), "r"(en) : "memory");
}
__device__ __forceinline__ void tmem_ld32(uint32_t* r, uint32_t addr) {
    asm volatile(
        "tcgen05.ld.sync.aligned.32x32b.x32.b32 "
        "{%0,%1,%2,%3,%4,%5,%6,%7,%8,%9,%10,%11,%12,%13,%14,%15,"
        "%16,%17,%18,%19,%20,%21,%22,%23,%24,%25,%26,%27,%28,%29,%30,%31}, [%32];"
        : "=r"(r[0]), "=r"(r[1]), "=r"(r[2]), "=r"(r[3]),
          "=r"(r[4]), "=r"(r[5]), "=r"(r[6]), "=r"(r[7]),
          "=r"(r[8]), "=r"(r[9]), "=r"(r[10]), "=r"(r[11]),
          "=r"(r[12]), "=r"(r[13]), "=r"(r[14]), "=r"(r[15]),
          "=r"(r[16]), "=r"(r[17]), "=r"(r[18]), "=r"(r[19]),
          "=r"(r[20]), "=r"(r[21]), "=r"(r[22]), "=r"(r[23]),
          "=r"(r[24]), "=r"(r[25]), "=r"(r[26]), "=r"(r[27]),
          "=r"(r[28]), "=r"(r[29]), "=r"(r[30]), "=r"(r[31])
        : "r"(addr));
}
__device__ __forceinline__ void cp16(uint32_t dst, const void* src) {
    asm volatile("cp.async.cg.shared.global [%0], [%1], 16;"
                 :: "r"(dst), "l"(src) : "memory");
}
#define CP_COMMIT()      asm volatile("cp.async.commit_group;" ::: "memory")
#define CP_WAIT(n)       asm volatile("cp.async.wait_group %0;" :: "n"(n) : "memory")
#define TC_WAIT_LD()      asm volatile("tcgen05.wait::ld.sync.aligned;" ::: "memory")
#define TC_FENCE_AFTER()  asm volatile("tcgen05.fence::after_thread_sync;" ::: "memory")
#define TC_FENCE_BEFORE() asm volatile("tcgen05.fence::before_thread_sync;" ::: "memory")
#define FENCE_ASYNC()     asm volatile("fence.proxy.async.shared::cta;" ::: "memory")
#endif  // TC_OK

#define SWZ(o) ((o) ^ (((o) >> 3) & 0x70))

__device__ __forceinline__ uint64_t mk_desc(uint32_t addr) {
    return (2ull << 61) | (1ull << 46) | (64ull << 32) | (1ull << 16)
         | ((uint64_t)(addr >> 4) & 0x3FFF);
}

// idesc: dtype=F32, a=BF16, b=BF16, N=256, M=128
static constexpr uint32_t IDESC =
    (1u << 4) | (1u << 7) | (1u << 10) | ((256u / 8) << 17) | ((128u / 16) << 24);

// SMEM layout (bytes from 1024-aligned base)
#define OFF_PTR   0
#define OFF_MB    16          // chunk mbars @16,24; tile mbars @32,40
#define OFF_AH(s) (1024 + (s) * 32768)
#define OFF_AL(s) (1024 + (s) * 32768 + 16384)
#define OFF_BH(s) (66560 + (s) * 65536)
#define OFF_BL(s) (66560 + (s) * 65536 + 32768)
#define TG_SMEM   198656

// ---------------- small kernels ---------------------------------------------
__global__ void k_zero(uint32_t* p, size_t n) {
    size_t i = (size_t)blockIdx.x * blockDim.x + threadIdx.x;
    if (i < n) p[i] = 0u;
}

__device__ __forceinline__ void bsplit(float w, __nv_bfloat16* H, __nv_bfloat16* L, int i) {
    __nv_bfloat16 h = __float2bfloat16(w);
    H[i] = h;
    L[i] = __float2bfloat16(w - __bfloat162float(h));
}

__global__ void k_pack(const float* __restrict__ Wz, const float* __restrict__ Wh,
                       const float* __restrict__ Ur, const float* __restrict__ Ow,
                       const int* __restrict__ fnode, const int* __restrict__ fmess,
                       int* __restrict__ mx) {
    int i = blockIdx.x * blockDim.x + threadIdx.x;
    int st = gridDim.x * blockDim.x;
    for (int t = i; t < 256 * 256; t += st) {
        int n = t >> 8, k = t & 255;
        bsplit(Ur[k * 256 + n],         g_BUh, g_BUl, t);
        bsplit(Wz[(256 + k) * 256 + n], g_BZh, g_BZl, t);
        bsplit(Wh[(256 + k) * 256 + n], g_BHh, g_BHl, t);
        bsplit(Ow[(256 + k) * 256 + n], g_BOh, g_BOl, t);
    }
    for (int t = i; t < M_MSG; t += st) mx[t] = fnode[fmess[t]];
}

// EX/EO tables: per-vocab precompute of all x-dependent matmuls.
__global__ void k_prep(const float* __restrict__ emb,
                       const float* __restrict__ Wz, const float* __restrict__ Wh,
                       const float* __restrict__ Wr, const float* __restrict__ Ow,
                       const float* __restrict__ Wzb, const float* __restrict__ Whb,
                       const float* __restrict__ Urb, const float* __restrict__ Ob,
                       float* __restrict__ EX, float* __restrict__ EO) {
    __shared__ float e[256];
    int v = blockIdx.x, j = threadIdx.x;
    e[j] = emb[v * 256 + j];
    __syncthreads();
    float s0 = 0, s1 = 0, s2 = 0, s3 = 0;
#pragma unroll 4
    for (int k = 0; k < 256; k++) {
        float ek = e[k];
        s0 = fmaf(ek, Wz[k * 256 + j], s0);
        s1 = fmaf(ek, Wh[k * 256 + j], s1);
        s2 = fmaf(ek, Wr[k * 256 + j], s2);
        s3 = fmaf(ek, Ow[k * 256 + j], s3);
    }
    EX[v * 768 + j]       = s0 + Wzb[j];
    EX[v * 768 + 256 + j] = s1 + Whb[j];
    EX[v * 768 + 512 + j] = s2 + Urb[j];
    EO[v * 256 + j]       = s3 + Ob[j];
}

// Gather: sum_h, sum_gh. 32 thr/msg, 8 cols each, uint4 loads.
__global__ void k_gather(const int* __restrict__ mg,
                         const __nv_bfloat16* __restrict__ rec,
                         const float* __restrict__ EX, const int* __restrict__ mx,
                         __nv_bfloat16* __restrict__ shh, __nv_bfloat16* __restrict__ shl,
                         __nv_bfloat16* __restrict__ sgh, __nv_bfloat16* __restrict__ sgl) {
    int gt = blockIdx.x * blockDim.x + threadIdx.x;
    int msg = gt >> 5;
    int j = gt & 31;
    if (msg >= M_MSG) return;
    int mxv = __ldg(mx + msg);
    float4 ra = *(const float4*)(EX + (size_t)mxv * 768 + 512 + j * 8);
    float4 rb = *(const float4*)(EX + (size_t)mxv * 768 + 512 + j * 8 + 4);
    float r1[8] = {ra.x, ra.y, ra.z, ra.w, rb.x, rb.y, rb.z, rb.w};
    float sh[8] = {0, 0, 0, 0, 0, 0, 0, 0};
    float sg[8] = {0, 0, 0, 0, 0, 0, 0, 0};
#pragma unroll
    for (int k = 0; k < 5; k++) {
        int gi = __ldg(mg + msg * 5 + k);
        const __nv_bfloat16* rp = rec + (size_t)gi * 768 + j * 8;
        uint4 hh = *(const uint4*)(rp);
        uint4 hl = *(const uint4*)(rp + 256);
        uint4 uu = *(const uint4*)(rp + 512);
        uint32_t hhw[4] = {hh.x, hh.y, hh.z, hh.w};
        uint32_t hlw[4] = {hl.x, hl.y, hl.z, hl.w};
        uint32_t uuw[4] = {uu.x, uu.y, uu.z, uu.w};
#pragma unroll
        for (int i = 0; i < 4; i++) {
            float h0 = bf_lo16(hhw[i]) + bf_lo16(hlw[i]);
            float h1 = bf_hi16(hhw[i]) + bf_hi16(hlw[i]);
            sh[i * 2 + 0] += h0;
            sh[i * 2 + 1] += h1;
            sg[i * 2 + 0] += sgm(r1[i * 2 + 0] + bf_lo16(uuw[i])) * h0;
            sg[i * 2 + 1] += sgm(r1[i * 2 + 1] + bf_hi16(uuw[i])) * h1;
        }
    }
    size_t o = (size_t)msg * 256 + j * 8;
    *(uint4*)(shh + o) = make_uint4(bf2pk(sh[0], sh[1]), bf2pk(sh[2], sh[3]),
                                    bf2pk(sh[4], sh[5]), bf2pk(sh[6], sh[7]));
    *(uint4*)(shl + o) = make_uint4(bf2pk(lo_of(sh[0]), lo_of(sh[1])), bf2pk(lo_of(sh[2]), lo_of(sh[3])),
                                    bf2pk(lo_of(sh[4]), lo_of(sh[5])), bf2pk(lo_of(sh[6]), lo_of(sh[7])));
    *(uint4*)(sgh + o) = make_uint4(bf2pk(sg[0], sg[1]), bf2pk(sg[2], sg[3]),
                                    bf2pk(sg[4], sg[5]), bf2pk(sg[6], sg[7]));
    *(uint4*)(sgl + o) = make_uint4(bf2pk(lo_of(sg[0]), lo_of(sg[1])), bf2pk(lo_of(sg[2]), lo_of(sg[3])),
                                    bf2pk(lo_of(sg[4]), lo_of(sg[5])), bf2pk(lo_of(sg[6]), lo_of(sg[7])));
}

// Per-node neighbor-message sum. 32 thr/node, uint4 loads.
__global__ void k_gnode(const int* __restrict__ ng,
                        const __nv_bfloat16* __restrict__ rec,
                        __nv_bfloat16* __restrict__ mnh, __nv_bfloat16* __restrict__ mnl) {
    int gt = blockIdx.x * blockDim.x + threadIdx.x;
    int n = gt >> 5;
    int j = gt & 31;
    if (n >= NNODE) return;
    float s[8] = {0, 0, 0, 0, 0, 0, 0, 0};
#pragma unroll
    for (int k = 0; k < 5; k++) {
        int gi = __ldg(ng + n * 5 + k);
        const __nv_bfloat16* rp = rec + (size_t)gi * 768 + j * 8;
        uint4 hh = *(const uint4*)(rp);
        uint4 hl = *(const uint4*)(rp + 256);
        uint32_t hhw[4] = {hh.x, hh.y, hh.z, hh.w};
        uint32_t hlw[4] = {hl.x, hl.y, hl.z, hl.w};
#pragma unroll
        for (int i = 0; i < 4; i++) {
            s[i * 2 + 0] += bf_lo16(hhw[i]) + bf_lo16(hlw[i]);
            s[i * 2 + 1] += bf_hi16(hhw[i]) + bf_hi16(hlw[i]);
        }
    }
    size_t o = (size_t)n * 256 + j * 8;
    *(uint4*)(mnh + o) = make_uint4(bf2pk(s[0], s[1]), bf2pk(s[2], s[3]),
                                    bf2pk(s[4], s[5]), bf2pk(s[6], s[7]));
    *(uint4*)(mnl + o) = make_uint4(bf2pk(lo_of(s[0]), lo_of(s[1])), bf2pk(lo_of(s[2]), lo_of(s[3])),
                                    bf2pk(lo_of(s[4]), lo_of(s[5])), bf2pk(lo_of(s[6]), lo_of(s[7])));
}

// Deterministic segment mean over sorted scope_ids.
__global__ void k_seg(const int* __restrict__ scope, const float* __restrict__ nv,
                      float* __restrict__ out) {
    int t = blockIdx.x;
    int j = threadIdx.x;
    int lo = 0, hi = NNODE;
    while (lo < hi) { int mid = (lo + hi) >> 1; if (scope[mid] < t) lo = mid + 1; else hi = mid; }
    int lo2 = lo, hi2 = NNODE;
    while (lo2 < hi2) { int mid = (lo2 + hi2) >> 1; if (scope[mid] < t + 1) lo2 = mid + 1; else hi2 = mid; }
    float s = 0.f;
    for (int r = lo; r < lo2; r++) s += nv[(size_t)r * HID + j];
    out[(size_t)t * HID + j] = s / fmaxf((float)(lo2 - lo), 1.f);
}

// ---------------- persistent tcgen05 GEMM (U / NV modes) --------------------
// 128x256 tile, fp32 TMEM acc, ping-pong deferred epilogue (as R12).
//   MODE 0 (U):  rec[m][512+col] = bf16(v)
//   MODE 3 (NV): nv = relu(EO[fn[m]] + v)
struct TG {
    const __nv_bfloat16 *Ah, *Al; int lda;
    const __nv_bfloat16 *Bh, *Bl;      // [256][256]
    __nv_bfloat16* rec;                // MODE 0 out
    const float* EO; const int* fn; float* nv;  // MODE 3
    int mT;
};

#if TC_OK
template <int MODE>
__device__ __forceinline__ void epi(const TG& p, uint32_t dbase, int m0, int tid) {
    int w = tid >> 5, l = tid & 31;
    int row = (w & 3) * 32 + l;
    int m = m0 + row;
    int chl = (w >> 2) * 128;
    int mxm = 0;
    if (MODE == 3) mxm = __ldg(p.fn + m);
#pragma unroll 1
    for (int cb = 0; cb < 4; cb++) {
        int col = chl + cb * 32;
        uint32_t rr[32];
        tmem_ld32(rr, dbase + col);
        TC_WAIT_LD();
        float v[32];
#pragma unroll
        for (int i = 0; i < 32; i++) v[i] = __uint_as_float(rr[i]);
        if (MODE == 0) {
            uint4* dst = (uint4*)(p.rec + (size_t)m * 768 + 512 + col);
#pragma unroll
            for (int i2 = 0; i2 < 4; i2++)
                dst[i2] = make_uint4(bf2pk(v[i2*8+0], v[i2*8+1]), bf2pk(v[i2*8+2], v[i2*8+3]),
                                     bf2pk(v[i2*8+4], v[i2*8+5]), bf2pk(v[i2*8+6], v[i2*8+7]));
        } else {
            const float4* eo4 = (const float4*)(p.EO + (size_t)mxm * 256 + col);
            float4* dst = (float4*)(p.nv + (size_t)m * 256 + col);
#pragma unroll
            for (int j2 = 0; j2 < 8; j2++) {
                float4 eo = eo4[j2];
                dst[j2] = make_float4(fmaxf(eo.x + v[j2*4+0], 0.f),
                                      fmaxf(eo.y + v[j2*4+1], 0.f),
                                      fmaxf(eo.z + v[j2*4+2], 0.f),
                                      fmaxf(eo.w + v[j2*4+3], 0.f));
            }
        }
    }
    TC_FENCE_BEFORE();
}
#endif

template <int MODE>
__global__ void __launch_bounds__(256) tgemm(TG p) {
    extern __shared__ char smraw[];
    char* sm = (char*)(((uintptr_t)smraw + 1023) & ~(uintptr_t)1023);
    const int tid = threadIdx.x;
#if TC_OK
    uint32_t sb = su32(sm);
    if (tid < 32) tc_alloc(sb + OFF_PTR, 512);
    if (tid == 0) {
        mbar_init(sb + OFF_MB + 0, 1);  mbar_init(sb + OFF_MB + 8, 1);
        mbar_init(sb + OFF_MB + 16, 1); mbar_init(sb + OFF_MB + 24, 1);
    }
    __syncthreads();
    uint32_t tmem = *(const uint32_t*)(sm + OFF_PTR);

    const int q = tid & 7, r8 = tid >> 3;

    int ph0 = 0, ph1 = 0, pend0 = 0, pend1 = 0;
    int tp0 = 0, tp1 = 0;
    int prev_m0 = -1, prev_db = 0;
    int lc = 0;

    for (int ti = blockIdx.x; ti < p.mT; ti += gridDim.x, lc++) {
        int m0 = ti * 128;
        int db = lc & 1;
        for (int c = 0; c < 4; c++) {
            int s = c & 1;
            if (s == 0) { if (pend0) { mbar_wait(sb + OFF_MB + 0, ph0); ph0 ^= 1; pend0 = 0; } }
            else        { if (pend1) { mbar_wait(sb + OFF_MB + 8, ph1); ph1 ^= 1; pend1 = 0; } }
            {
                const __nv_bfloat16* Ah = p.Ah + (size_t)m0 * p.lda + c * 64 + q * 8;
                const __nv_bfloat16* Al = p.Al + (size_t)m0 * p.lda + c * 64 + q * 8;
#pragma unroll
                for (int u = 0; u < 4; u++) {
                    int row = u * 32 + r8;
                    uint32_t sw = SWZ((uint32_t)(row * 128 + q * 16));
                    cp16(sb + OFF_AH(s) + sw, Ah + (size_t)row * p.lda);
                    cp16(sb + OFF_AL(s) + sw, Al + (size_t)row * p.lda);
                }
            }
            {
                const __nv_bfloat16* Bh = p.Bh + c * 64 + q * 8;
                const __nv_bfloat16* Bl = p.Bl + c * 64 + q * 8;
#pragma unroll
                for (int u = 0; u < 8; u++) {
                    int row = u * 32 + r8;
                    uint32_t sw = SWZ((uint32_t)(row * 128 + q * 16));
                    cp16(sb + OFF_BH(s) + sw, Bh + (size_t)row * 256);
                    cp16(sb + OFF_BL(s) + sw, Bl + (size_t)row * 256);
                }
            }
            CP_COMMIT();
            if (c >= 1) {
                CP_WAIT(1);
                __syncthreads();
                FENCE_ASYNC();
                int sp = s ^ 1;
                if (tid < 32 && elect1()) {
                    uint64_t ah = mk_desc(sb + OFF_AH(sp));
                    uint64_t al = mk_desc(sb + OFF_AL(sp));
                    uint64_t bh = mk_desc(sb + OFF_BH(sp));
                    uint64_t bl = mk_desc(sb + OFF_BL(sp));
                    uint32_t d = tmem + db * 256;
#pragma unroll
                    for (int k = 0; k < 4; k++) {
                        bool acc = (c > 1) || (k > 0);
                        mma_f16_ss(d, ah + k * 2, bh + k * 2, IDESC, acc);
                        mma_f16_ss(d, al + k * 2, bh + k * 2, IDESC, true);
                        mma_f16_ss(d, ah + k * 2, bl + k * 2, IDESC, true);
                    }
                    tc_commit(sb + OFF_MB + sp * 8);
                }
                if (sp) pend1 = 1; else pend0 = 1;
            }
        }
        CP_WAIT(0);
        __syncthreads();
        FENCE_ASYNC();
        if (tid < 32 && elect1()) {
            uint64_t ah = mk_desc(sb + OFF_AH(1));
            uint64_t al = mk_desc(sb + OFF_AL(1));
            uint64_t bh = mk_desc(sb + OFF_BH(1));
            uint64_t bl = mk_desc(sb + OFF_BL(1));
            uint32_t d = tmem + db * 256;
#pragma unroll
            for (int k = 0; k < 4; k++) {
                mma_f16_ss(d, ah + k * 2, bh + k * 2, IDESC, true);
                mma_f16_ss(d, al + k * 2, bh + k * 2, IDESC, true);
                mma_f16_ss(d, ah + k * 2, bl + k * 2, IDESC, true);
            }
            tc_commit(sb + OFF_MB + 8);
            tc_commit(sb + OFF_MB + 16 + db * 8);
        }
        pend1 = 1;
        if (prev_m0 >= 0) {
            if (prev_db == 0) { mbar_wait(sb + OFF_MB + 16, tp0); tp0 ^= 1; }
            else              { mbar_wait(sb + OFF_MB + 24, tp1); tp1 ^= 1; }
            TC_FENCE_AFTER();
            epi<MODE>(p, tmem + prev_db * 256, prev_m0, tid);
        }
        prev_m0 = m0; prev_db = db;
    }
    if (prev_m0 >= 0) {
        if (prev_db == 0) { mbar_wait(sb + OFF_MB + 16, tp0); tp0 ^= 1; }
        else              { mbar_wait(sb + OFF_MB + 24, tp1); tp1 ^= 1; }
        TC_FENCE_AFTER();
        epi<MODE>(p, tmem + prev_db * 256, prev_m0, tid);
    }
    __syncthreads();
    if (tid < 32) tc_dealloc(tmem, 512);
#else
    for (int ti = blockIdx.x; ti < p.mT; ti += gridDim.x) {
        int m0 = ti * 128;
        for (int e = tid; e < 128 * 256; e += 256) {
            int r = e >> 8, col = e & 255;
            int m = m0 + r;
            float acc = 0.f;
            for (int k = 0; k < 256; k++) {
                float a = __bfloat162float(p.Ah[(size_t)m * p.lda + k])
                        + __bfloat162float(p.Al[(size_t)m * p.lda + k]);
                float b = __bfloat162float(p.Bh[(size_t)col * 256 + k])
                        + __bfloat162float(p.Bl[(size_t)col * 256 + k]);
                acc += a * b;
            }
            if (MODE == 0) {
                p.rec[(size_t)m * 768 + 512 + col] = __float2bfloat16(acc);
            } else {
                int fn = p.fn[m];
                p.nv[(size_t)m * 256 + col] =
                    fmaxf(p.EO[(size_t)fn * 256 + col] + acc, 0.f);
            }
        }
    }
#endif
}

// ---------------- merged Z+H tcgen05 GEMM ------------------------------------
// Per 128-row tile: Zacc(tmem 0-255) = sum_h @ Wzh^T ; Hacc(tmem 256-511) =
// sum_gh @ Whh^T (8 K-chunks). One epilogue: z = sigmoid(EXz+vz) in regs,
// h = (1-z)*sum_h + z*tanh(EXh+vh); mask row0; write rec h planes.
struct TZ {
    const __nv_bfloat16 *shh, *shl;    // sum_h planes (A phase 0 + epi input)
    const __nv_bfloat16 *sgh, *sgl;    // sum_gh planes (A phase 1)
    const __nv_bfloat16 *BZh, *BZl, *BHh, *BHl;
    __nv_bfloat16* rec;
    const float* EX; const int* mx;
    int mT;
};

__global__ void __launch_bounds__(256) tgemmZH(TZ p) {
    extern __shared__ char smraw[];
    char* sm = (char*)(((uintptr_t)smraw + 1023) & ~(uintptr_t)1023);
    const int tid = threadIdx.x;
#if TC_OK
    uint32_t sb = su32(sm);
    if (tid < 32) tc_alloc(sb + OFF_PTR, 512);
    if (tid == 0) {
        mbar_init(sb + OFF_MB + 0, 1);  mbar_init(sb + OFF_MB + 8, 1);
        mbar_init(sb + OFF_MB + 16, 1);
    }
    __syncthreads();
    uint32_t tmem = *(const uint32_t*)(sm + OFF_PTR);

    const int q = tid & 7, r8 = tid >> 3;

    int ph0 = 0, ph1 = 0, pend0 = 0, pend1 = 0, tp = 0;

    for (int ti = blockIdx.x; ti < p.mT; ti += gridDim.x) {
        int m0 = ti * 128;
        for (int cc = 0; cc < 8; cc++) {
            int s = cc & 1;
            int phase = cc >> 2, c = cc & 3;
            if (s == 0) { if (pend0) { mbar_wait(sb + OFF_MB + 0, ph0); ph0 ^= 1; pend0 = 0; } }
            else        { if (pend1) { mbar_wait(sb + OFF_MB + 8, ph1); ph1 ^= 1; pend1 = 0; } }
            {
                const __nv_bfloat16* Ah = (phase ? p.sgh : p.shh) + (size_t)m0 * 256 + c * 64 + q * 8;
                const __nv_bfloat16* Al = (phase ? p.sgl : p.shl) + (size_t)m0 * 256 + c * 64 + q * 8;
#pragma unroll
                for (int u = 0; u < 4; u++) {
                    int row = u * 32 + r8;
                    uint32_t sw = SWZ((uint32_t)(row * 128 + q * 16));
                    cp16(sb + OFF_AH(s) + sw, Ah + (size_t)row * 256);
                    cp16(sb + OFF_AL(s) + sw, Al + (size_t)row * 256);
                }
                const __nv_bfloat16* Bh = (phase ? p.BHh : p.BZh) + c * 64 + q * 8;
                const __nv_bfloat16* Bl = (phase ? p.BHl : p.BZl) + c * 64 + q * 8;
#pragma unroll
                for (int u = 0; u < 8; u++) {
                    int row = u * 32 + r8;
                    uint32_t sw = SWZ((uint32_t)(row * 128 + q * 16));
                    cp16(sb + OFF_BH(s) + sw, Bh + (size_t)row * 256);
                    cp16(sb + OFF_BL(s) + sw, Bl + (size_t)row * 256);
                }
            }
            CP_COMMIT();
            if (cc >= 1) {
                CP_WAIT(1);
                __syncthreads();
                FENCE_ASYNC();
                int pc = cc - 1;               // chunk whose MMA we issue now
                int sp = pc & 1;
                if (tid < 32 && elect1()) {
                    uint64_t ah = mk_desc(sb + OFF_AH(sp));
                    uint64_t al = mk_desc(sb + OFF_AL(sp));
                    uint64_t bh = mk_desc(sb + OFF_BH(sp));
                    uint64_t bl = mk_desc(sb + OFF_BL(sp));
                    uint32_t d = tmem + (pc >> 2) * 256;
                    bool first = (pc & 3) == 0;
#pragma unroll
                    for (int k = 0; k < 4; k++) {
                        bool acc = !first || (k > 0);
                        mma_f16_ss(d, ah + k * 2, bh + k * 2, IDESC, acc);
                        mma_f16_ss(d, al + k * 2, bh + k * 2, IDESC, true);
                        mma_f16_ss(d, ah + k * 2, bl + k * 2, IDESC, true);
                    }
                    tc_commit(sb + OFF_MB + sp * 8);
                }
                if (sp) pend1 = 1; else pend0 = 1;
            }
        }
        // tail: MMA of chunk 7 (buffer 1, H phase, acc)
        CP_WAIT(0);
        __syncthreads();
        FENCE_ASYNC();
        if (tid < 32 && elect1()) {
            uint64_t ah = mk_desc(sb + OFF_AH(1));
            uint64_t al = mk_desc(sb + OFF_AL(1));
            uint64_t bh = mk_desc(sb + OFF_BH(1));
            uint64_t bl = mk_desc(sb + OFF_BL(1));
            uint32_t d = tmem + 256;
#pragma unroll
            for (int k = 0; k < 4; k++) {
                mma_f16_ss(d, ah + k * 2, bh + k * 2, IDESC, true);
                mma_f16_ss(d, al + k * 2, bh + k * 2, IDESC, true);
                mma_f16_ss(d, ah + k * 2, bl + k * 2, IDESC, true);
            }
            tc_commit(sb + OFF_MB + 8);
            tc_commit(sb + OFF_MB + 16);
        }
        pend1 = 1;
        // combined epilogue (not deferred — both accumulators in use)
        mbar_wait(sb + OFF_MB + 16, tp); tp ^= 1;
        TC_FENCE_AFTER();
        {
            int w = tid >> 5, l = tid & 31;
            int row = (w & 3) * 32 + l;
            int m = m0 + row;
            int chl = (w >> 2) * 128;
            int mxm = __ldg(p.mx + m);
            const float* exrow = p.EX + (size_t)mxm * 768;
#pragma unroll 1
            for (int cb = 0; cb < 4; cb++) {
                int col = chl + cb * 32;
                uint32_t rz[32], rh[32];
                tmem_ld32(rz, tmem + col);
                tmem_ld32(rh, tmem + 256 + col);
                TC_WAIT_LD();
                const float4* exz4 = (const float4*)(exrow + col);
                const float4* exh4 = (const float4*)(exrow + 256 + col);
                const uint4* shh4 = (const uint4*)(p.shh + (size_t)m * 256 + col);
                const uint4* shl4 = (const uint4*)(p.shl + (size_t)m * 256 + col);
                uint4* hdh = (uint4*)(p.rec + (size_t)m * 768 + col);
                uint4* hdl = (uint4*)(p.rec + (size_t)m * 768 + 256 + col);
#pragma unroll
                for (int j2 = 0; j2 < 4; j2++) {   // 8 cols per group
                    float4 za = exz4[j2 * 2], zb = exz4[j2 * 2 + 1];
                    float4 ha = exh4[j2 * 2], hb = exh4[j2 * 2 + 1];
                    uint4 sh = shh4[j2], sl = shl4[j2];
                    float exz[8] = {za.x, za.y, za.z, za.w, zb.x, zb.y, zb.z, zb.w};
                    float exh[8] = {ha.x, ha.y, ha.z, ha.w, hb.x, hb.y, hb.z, hb.w};
                    uint32_t shw[4] = {sh.x, sh.y, sh.z, sh.w};
                    uint32_t slw[4] = {sl.x, sl.y, sl.z, sl.w};
                    float h[8];
#pragma unroll
                    for (int i = 0; i < 8; i++) {
                        float su = ((i & 1) ? bf_hi16(shw[i >> 1]) : bf_lo16(shw[i >> 1]))
                                 + ((i & 1) ? bf_hi16(slw[i >> 1]) : bf_lo16(slw[i >> 1]));
                        float z = sgm(exz[i] + __uint_as_float(rz[j2 * 8 + i]));
                        h[i] = (1.f - z) * su
                             + z * tanhf(exh[i] + __uint_as_float(rh[j2 * 8 + i]));
                        if (m == 0) h[i] = 0.f;
                    }
                    hdh[j2] = make_uint4(bf2pk(h[0], h[1]), bf2pk(h[2], h[3]),
                                         bf2pk(h[4], h[5]), bf2pk(h[6], h[7]));
                    hdl[j2] = make_uint4(bf2pk(lo_of(h[0]), lo_of(h[1])), bf2pk(lo_of(h[2]), lo_of(h[3])),
                                         bf2pk(lo_of(h[4]), lo_of(h[5])), bf2pk(lo_of(h[6]), lo_of(h[7])));
                }
            }
            TC_FENCE_BEFORE();
        }
        // next tile's first MMA issues only after a __syncthreads (cc=1 path),
        // so all warps' TMEM reads are complete before accumulator reuse.
    }
    __syncthreads();
    if (tid < 32) tc_dealloc(tmem, 512);
#else
    for (int ti = blockIdx.x; ti < p.mT; ti += gridDim.x) {
        int m0 = ti * 128;
        for (int e = tid; e < 128 * 256; e += 256) {
            int r = e >> 8, col = e & 255;
            int m = m0 + r;
            float az = 0.f, ah = 0.f;
            for (int k = 0; k < 256; k++) {
                float sh = __bfloat162float(p.shh[(size_t)m * 256 + k])
                         + __bfloat162float(p.shl[(size_t)m * 256 + k]);
                float sg = __bfloat162float(p.sgh[(size_t)m * 256 + k])
                         + __bfloat162float(p.sgl[(size_t)m * 256 + k]);
                az += sh * (__bfloat162float(p.BZh[(size_t)col * 256 + k])
                          + __bfloat162float(p.BZl[(size_t)col * 256 + k]));
                ah += sg * (__bfloat162float(p.BHh[(size_t)col * 256 + k])
                          + __bfloat162float(p.BHl[(size_t)col * 256 + k]));
            }
            int mxm = p.mx[m];
            float z = sgm(p.EX[(size_t)mxm * 768 + col] + az);
            float su = __bfloat162float(p.shh[(size_t)m * 256 + col])
                     + __bfloat162float(p.shl[(size_t)m * 256 + col]);
            float h = (1.f - z) * su
                    + z * tanhf(p.EX[(size_t)mxm * 768 + 256 + col] + ah);
            if (m == 0) h = 0.f;
            __nv_bfloat16 hb = __float2bfloat16(h);
            p.rec[(size_t)m * 768 + col] = hb;
            p.rec[(size_t)m * 768 + 256 + col] =
                __float2bfloat16(h - __bfloat162float(hb));
        }
    }
#endif
}

// ---------------- orchestration --------------------------------------------
extern "C" void kernel_launch(void* const* d_in, const int* in_sizes, int n_in,
                              void* d_out, int out_size) {
    const int*   fnode = (const int*)d_in[0];
    const int*   fmess = (const int*)d_in[1];
    const int*   ng    = (const int*)d_in[2];
    const int*   mg    = (const int*)d_in[3];
    const int*   scope = (const int*)d_in[4];
    const float* emb   = (const float*)d_in[5];
    const float* Wz    = (const float*)d_in[6];
    const float* Wzb   = (const float*)d_in[7];
    const float* Wr    = (const float*)d_in[8];
    const float* Ur    = (const float*)d_in[9];
    const float* Urb   = (const float*)d_in[10];
    const float* Wh    = (const float*)d_in[11];
    const float* Whb   = (const float*)d_in[12];
    const float* Ow    = (const float*)d_in[13];
    const float* Ob    = (const float*)d_in[14];
    float* out = (float*)d_out;

    __nv_bfloat16 *rec, *shh, *shl, *sgh, *sgl, *mnh, *mnl;
    __nv_bfloat16 *BUh, *BUl, *BZh, *BZl, *BHh, *BHl, *BOh, *BOl;
    float *nv, *EX, *EO;
    int* mx;
    cudaGetSymbolAddress((void**)&rec, g_rec);
    cudaGetSymbolAddress((void**)&shh, g_shh); cudaGetSymbolAddress((void**)&shl, g_shl);
    cudaGetSymbolAddress((void**)&sgh, g_sgh); cudaGetSymbolAddress((void**)&sgl, g_sgl);
    cudaGetSymbolAddress((void**)&mnh, g_mnh); cudaGetSymbolAddress((void**)&mnl, g_mnl);
    cudaGetSymbolAddress((void**)&nv,  g_nv);
    cudaGetSymbolAddress((void**)&EX,  g_EX);
    cudaGetSymbolAddress((void**)&EO,  g_EO);
    cudaGetSymbolAddress((void**)&mx,  g_mx);
    cudaGetSymbolAddress((void**)&BUh, g_BUh); cudaGetSymbolAddress((void**)&BUl, g_BUl);
    cudaGetSymbolAddress((void**)&BZh, g_BZh); cudaGetSymbolAddress((void**)&BZl, g_BZl);
    cudaGetSymbolAddress((void**)&BHh, g_BHh); cudaGetSymbolAddress((void**)&BHl, g_BHl);
    cudaGetSymbolAddress((void**)&BOh, g_BOh); cudaGetSymbolAddress((void**)&BOl, g_BOl);

    cudaFuncSetAttribute(tgemm<0>, cudaFuncAttributeMaxDynamicSharedMemorySize, TG_SMEM);
    cudaFuncSetAttribute(tgemm<3>, cudaFuncAttributeMaxDynamicSharedMemorySize, TG_SMEM);
    cudaFuncSetAttribute(tgemmZH, cudaFuncAttributeMaxDynamicSharedMemorySize, TG_SMEM);

    size_t recw = (size_t)M_MSG * 768 * 2 / 4;
    k_zero<<<(unsigned)((recw + 255) / 256), 256>>>((uint32_t*)rec, recw);
    k_pack<<<512, 256>>>(Wz, Wh, Ur, Ow, fnode, fmess, mx);
    k_prep<<<780, 256>>>(emb, Wz, Wh, Wr, Ow, Wzb, Whb, Urb, Ob, EX, EO);

    for (int d = 0; d < DEPTH; d++) {
        // U = h @ Ur  -> rec[:,512:768]
        TG pU{}; pU.Ah = rec; pU.Al = rec + 256; pU.lda = 768;
        pU.Bh = BUh; pU.Bl = BUl; pU.rec = rec; pU.mT = M_MSG / 128;
        tgemm<0><<<GRID_P, 256, TG_SMEM>>>(pU);
        // gather: sum_h, sum_gh
        k_gather<<<(M_MSG * 32) / 256, 256>>>(mg, rec, EX, mx, shh, shl, sgh, sgl);
        // merged: z = sigmoid(EXz + sum_h@Wzh); h = (1-z)sum_h + z tanh(EXh + sum_gh@Whh)
        TZ pZ{}; pZ.shh = shh; pZ.shl = shl; pZ.sgh = sgh; pZ.sgl = sgl;
        pZ.BZh = BZh; pZ.BZl = BZl; pZ.BHh = BHh; pZ.BHl = BHl;
        pZ.rec = rec; pZ.EX = EX; pZ.mx = mx; pZ.mT = M_MSG / 128;
        tgemmZH<<<GRID_P, 256, TG_SMEM>>>(pZ);
    }

    // mess_nei per node
    k_gnode<<<(NNODE * 32) / 256, 256>>>(ng, rec, mnh, mnl);

    // node_vec = relu(EO[fnode] + mn @ Ow2)
    TG pN{}; pN.Ah = mnh; pN.Al = mnl; pN.lda = 256;
    pN.Bh = BOh; pN.Bl = BOl; pN.EO = EO; pN.fn = fnode; pN.nv = nv;
    pN.mT = NNODE / 128;
    tgemm<3><<<GRID_P, 256, TG_SMEM>>>(pN);

    // segment mean (sorted scopes, deterministic)
    k_seg<<<NTREE, 256>>>(scope, nv, out);
}

// round 14
// speedup vs baseline: 1.2306x; 1.2306x over previous
#include <cuda_runtime.h>
#include <cuda_bf16.h>
#include <cstdint>
#include <cstddef>

#define M_MSG 131072
#define NNODE 65536
#define HID   256
#define DEPTH 6
#define NTREE 2048
#define GRID_P 148

#if defined(__CUDA_ARCH_FEAT_SM103_ALL) || defined(__CUDA_ARCH_FEAT_SM100_ALL) || \
    defined(__CUDA_ARCH_FEAT_SM101_ALL) || defined(__CUDA_ARCH_FEAT_SM110_ALL)
#define TC_OK 1
#else
#define TC_OK 0
#endif

// ---------------- static device scratch ------------------------------------
// Per-message record: [0:256) h_hi | [256:512) h_lo | [512:768) U   (bf16)
__device__ __nv_bfloat16 g_rec[(size_t)M_MSG * 768];
// GEMM A operands as bf16 hi/lo planes
__device__ __nv_bfloat16 g_shh[(size_t)M_MSG * 256], g_shl[(size_t)M_MSG * 256]; // sum_h
__device__ __nv_bfloat16 g_sgh[(size_t)M_MSG * 256], g_sgl[(size_t)M_MSG * 256]; // sum_gh
__device__ __nv_bfloat16 g_mnh[(size_t)NNODE * 256], g_mnl[(size_t)NNODE * 256]; // mess_nei
__device__ unsigned short g_zu[(size_t)M_MSG * 256];  // z gate u16 fixed point
__device__ float g_nv[(size_t)NNODE * 256];           // node_vec
__device__ float g_EX[780 * 768];                     // emb@[Wzx|Whx|Wr]+biases
__device__ float g_EO[780 * 256];                     // emb@Ow1+Ob
__device__ int   g_mx[M_MSG];                         // fnode[fmess[m]]
// bf16 hi/lo split weights, [n][k] layout (B operand = W^T), all 256x256
__device__ __nv_bfloat16 g_BUh[256 * 256], g_BUl[256 * 256];  // Ur^T
__device__ __nv_bfloat16 g_BZh[256 * 256], g_BZl[256 * 256];  // Wzh^T
__device__ __nv_bfloat16 g_BHh[256 * 256], g_BHl[256 * 256];  // Whh^T
__device__ __nv_bfloat16 g_BOh[256 * 256], g_BOl[256 * 256];  // Ow2^T

// ---------------- bf16 helpers ----------------------------------------------
__device__ __forceinline__ float bf_lo16(uint32_t u) { return __uint_as_float(u << 16); }
__device__ __forceinline__ float bf_hi16(uint32_t u) { return __uint_as_float(u & 0xFFFF0000u); }
__device__ __forceinline__ uint32_t bf2pk(float a, float b) {
    return (uint32_t)__bfloat16_as_ushort(__float2bfloat16(a))
         | ((uint32_t)__bfloat16_as_ushort(__float2bfloat16(b)) << 16);
}
__device__ __forceinline__ float lo_of(float v) {
    return v - __bfloat162float(__float2bfloat16(v));
}
__device__ __forceinline__ float sgm(float x) { return 1.0f / (1.0f + __expf(-x)); }

// ---------------- PTX helpers ------------------------------------------------
__device__ __forceinline__ uint32_t su32(const void* p) {
    uint32_t a;
    asm("{ .reg .u64 t; cvta.to.shared.u64 t, %1; cvt.u32.u64 %0, t; }"
        : "=r"(a) : "l"(p));
    return a;
}
#if TC_OK
__device__ __forceinline__ bool elect1() {
    uint32_t p;
    asm volatile("{\n\t.reg .pred p;\n\telect.sync _|p, 0xFFFFFFFF;\n\t"
                 "selp.b32 %0, 1, 0, p;\n\t}" : "=r"(p));
    return p != 0;
}
__device__ __forceinline__ void mbar_init(uint32_t a, uint32_t cnt) {
    asm volatile("mbarrier.init.shared.b64 [%0], %1;" :: "r"(a), "r"(cnt) : "memory");
}
__device__ __forceinline__ void mbar_wait(uint32_t a, int par) {
    asm volatile(
        "{\n\t.reg .pred P;\n"
        "W%=:\n\t"
        "mbarrier.try_wait.parity.acquire.cta.shared::cta.b64 P, [%0], %1, 0x989680;\n\t"
        "@P bra.uni D%=;\n\t"
        "bra.uni W%=;\n"
        "D%=:\n\t}" :: "r"(a), "r"(par) : "memory");
}
__device__ __forceinline__ void tc_alloc(uint32_t smem_res, uint32_t ncols) {
    asm volatile("tcgen05.alloc.cta_group::1.sync.aligned.shared::cta.b32 [%0], %1;"
                 :: "r"(smem_res), "r"(ncols) : "memory");
}
__device__ __forceinline__ void tc_dealloc(uint32_t tmem, uint32_t ncols) {
    asm volatile("tcgen05.dealloc.cta_group::1.sync.aligned.b32 %0, %1;"
                 :: "r"(tmem), "r"(ncols));
}
__device__ __forceinline__ void tc_commit(uint32_t mbar) {
    asm volatile("tcgen05.commit.cta_group::1.mbarrier::arrive::one.shared::cluster.b64 [%0];"
                 :: "r"(mbar) : "memory");
}
__device__ __forceinline__ void mma_f16_ss(uint32_t d, uint64_t ad, uint64_t bd,
                                           uint32_t idesc, bool acc) {
    uint32_t en = acc ? 1u : 0u;
    asm volatile(
        "{\n\t.reg .pred p;\n\tsetp.ne.u32 p, %5, 0;\n\t"
        "tcgen05.mma.cta_group::1.kind::f16 [%0], %1, %2, %3, {%4, %4, %4, %4}, p;\n\t}"
        :: "r"(d), "l"(ad), "l"(bd), "r"(idesc), "r"(0u), "r"(en) : "memory");
}
__device__ __forceinline__ void tmem_ld32(uint32_t* r, uint32_t addr) {
    asm volatile(
        "tcgen05.ld.sync.aligned.32x32b.x32.b32 "
        "{%0,%1,%2,%3,%4,%5,%6,%7,%8,%9,%10,%11,%12,%13,%14,%15,"
        "%16,%17,%18,%19,%20,%21,%22,%23,%24,%25,%26,%27,%28,%29,%30,%31}, [%32];"
        : "=r"(r[0]), "=r"(r[1]), "=r"(r[2]), "=r"(r[3]),
          "=r"(r[4]), "=r"(r[5]), "=r"(r[6]), "=r"(r[7]),
          "=r"(r[8]), "=r"(r[9]), "=r"(r[10]), "=r"(r[11]),
          "=r"(r[12]), "=r"(r[13]), "=r"(r[14]), "=r"(r[15]),
          "=r"(r[16]), "=r"(r[17]), "=r"(r[18]), "=r"(r[19]),
          "=r"(r[20]), "=r"(r[21]), "=r"(r[22]), "=r"(r[23]),
          "=r"(r[24]), "=r"(r[25]), "=r"(r[26]), "=r"(r[27]),
          "=r"(r[28]), "=r"(r[29]), "=r"(r[30]), "=r"(r[31])
        : "r"(addr));
}
__device__ __forceinline__ void cp16(uint32_t dst, const void* src) {
    asm volatile("cp.async.cg.shared.global [%0], [%1], 16;"
                 :: "r"(dst), "l"(src) : "memory");
}
#define CP_COMMIT()      asm volatile("cp.async.commit_group;" ::: "memory")
#define CP_WAIT(n)       asm volatile("cp.async.wait_group %0;" :: "n"(n) : "memory")
#define TC_WAIT_LD()      asm volatile("tcgen05.wait::ld.sync.aligned;" ::: "memory")
#define TC_FENCE_AFTER()  asm volatile("tcgen05.fence::after_thread_sync;" ::: "memory")
#define TC_FENCE_BEFORE() asm volatile("tcgen05.fence::before_thread_sync;" ::: "memory")
#define FENCE_ASYNC()     asm volatile("fence.proxy.async.shared::cta;" ::: "memory")
#endif  // TC_OK

#define SWZ(o) ((o) ^ (((o) >> 3) & 0x70))

__device__ __forceinline__ uint64_t mk_desc(uint32_t addr) {
    return (2ull << 61) | (1ull << 46) | (64ull << 32) | (1ull << 16)
         | ((uint64_t)(addr >> 4) & 0x3FFF);
}

// idesc: dtype=F32, a=BF16, b=BF16, N=256, M=128
static constexpr uint32_t IDESC =
    (1u << 4) | (1u << 7) | (1u << 10) | ((256u / 8) << 17) | ((128u / 16) << 24);

// SMEM layout (bytes from 1024-aligned base)
#define OFF_PTR   0
#define OFF_MB    16          // chunk mbars @16,24; tile mbars @32,40
#define OFF_AH(s) (1024 + (s) * 32768)
#define OFF_AL(s) (1024 + (s) * 32768 + 16384)
#define OFF_BH(s) (66560 + (s) * 65536)
#define OFF_BL(s) (66560 + (s) * 65536 + 32768)
#define TG_SMEM   198656

// ---------------- small kernels ---------------------------------------------
__global__ void k_zero(uint32_t* p, size_t n) {
    size_t i = (size_t)blockIdx.x * blockDim.x + threadIdx.x;
    if (i < n) p[i] = 0u;
}

__device__ __forceinline__ void bsplit(float w, __nv_bfloat16* H, __nv_bfloat16* L, int i) {
    __nv_bfloat16 h = __float2bfloat16(w);
    H[i] = h;
    L[i] = __float2bfloat16(w - __bfloat162float(h));
}

__global__ void k_pack(const float* __restrict__ Wz, const float* __restrict__ Wh,
                       const float* __restrict__ Ur, const float* __restrict__ Ow,
                       const int* __restrict__ fnode, const int* __restrict__ fmess,
                       int* __restrict__ mx) {
    int i = blockIdx.x * blockDim.x + threadIdx.x;
    int st = gridDim.x * blockDim.x;
    for (int t = i; t < 256 * 256; t += st) {
        int n = t >> 8, k = t & 255;
        bsplit(Ur[k * 256 + n],         g_BUh, g_BUl, t);
        bsplit(Wz[(256 + k) * 256 + n], g_BZh, g_BZl, t);
        bsplit(Wh[(256 + k) * 256 + n], g_BHh, g_BHl, t);
        bsplit(Ow[(256 + k) * 256 + n], g_BOh, g_BOl, t);
    }
    for (int t = i; t < M_MSG; t += st) mx[t] = fnode[fmess[t]];
}

// EX/EO tables: per-vocab precompute of all x-dependent matmuls.
__global__ void k_prep(const float* __restrict__ emb,
                       const float* __restrict__ Wz, const float* __restrict__ Wh,
                       const float* __restrict__ Wr, const float* __restrict__ Ow,
                       const float* __restrict__ Wzb, const float* __restrict__ Whb,
                       const float* __restrict__ Urb, const float* __restrict__ Ob,
                       float* __restrict__ EX, float* __restrict__ EO) {
    __shared__ float e[256];
    int v = blockIdx.x, j = threadIdx.x;
    e[j] = emb[v * 256 + j];
    __syncthreads();
    float s0 = 0, s1 = 0, s2 = 0, s3 = 0;
#pragma unroll 4
    for (int k = 0; k < 256; k++) {
        float ek = e[k];
        s0 = fmaf(ek, Wz[k * 256 + j], s0);
        s1 = fmaf(ek, Wh[k * 256 + j], s1);
        s2 = fmaf(ek, Wr[k * 256 + j], s2);
        s3 = fmaf(ek, Ow[k * 256 + j], s3);
    }
    EX[v * 768 + j]       = s0 + Wzb[j];
    EX[v * 768 + 256 + j] = s1 + Whb[j];
    EX[v * 768 + 512 + j] = s2 + Urb[j];
    EO[v * 256 + j]       = s3 + Ob[j];
}

// Gather: sum_h, sum_gh. 64 thr/msg. All 15 loads hoisted ahead of the math
// (MLP 15 instead of 3) — latency-bound kernel, same bytes, same arithmetic.
__global__ void k_gather(const int* __restrict__ mg,
                         const __nv_bfloat16* __restrict__ rec,
                         const float* __restrict__ EX, const int* __restrict__ mx,
                         __nv_bfloat16* __restrict__ shh, __nv_bfloat16* __restrict__ shl,
                         __nv_bfloat16* __restrict__ sgh, __nv_bfloat16* __restrict__ sgl) {
    int gt = blockIdx.x * blockDim.x + threadIdx.x;
    int msg = gt >> 6;
    int j = gt & 63;
    if (msg >= M_MSG) return;
    int mxv = __ldg(mx + msg);
    int gi[5];
#pragma unroll
    for (int k = 0; k < 5; k++) gi[k] = __ldg(mg + msg * 5 + k);
    // issue all neighbor loads up front
    uint2 hh[5], hl[5], uu[5];
#pragma unroll
    for (int k = 0; k < 5; k++) {
        const __nv_bfloat16* rp = rec + (size_t)gi[k] * 768 + j * 4;
        hh[k] = *(const uint2*)(rp);
        hl[k] = *(const uint2*)(rp + 256);
        uu[k] = *(const uint2*)(rp + 512);
    }
    float4 r1 = *(const float4*)(EX + (size_t)mxv * 768 + 512 + j * 4);
    float sh0 = 0, sh1 = 0, sh2 = 0, sh3 = 0;
    float sg0 = 0, sg1 = 0, sg2 = 0, sg3 = 0;
#pragma unroll
    for (int k = 0; k < 5; k++) {
        float h0 = bf_lo16(hh[k].x) + bf_lo16(hl[k].x);
        float h1 = bf_hi16(hh[k].x) + bf_hi16(hl[k].x);
        float h2 = bf_lo16(hh[k].y) + bf_lo16(hl[k].y);
        float h3 = bf_hi16(hh[k].y) + bf_hi16(hl[k].y);
        sh0 += h0; sh1 += h1; sh2 += h2; sh3 += h3;
        sg0 += sgm(r1.x + bf_lo16(uu[k].x)) * h0;
        sg1 += sgm(r1.y + bf_hi16(uu[k].x)) * h1;
        sg2 += sgm(r1.z + bf_lo16(uu[k].y)) * h2;
        sg3 += sgm(r1.w + bf_hi16(uu[k].y)) * h3;
    }
    size_t o = (size_t)msg * 256 + j * 4;
    *(uint2*)(shh + o) = make_uint2(bf2pk(sh0, sh1), bf2pk(sh2, sh3));
    *(uint2*)(shl + o) = make_uint2(bf2pk(lo_of(sh0), lo_of(sh1)), bf2pk(lo_of(sh2), lo_of(sh3)));
    *(uint2*)(sgh + o) = make_uint2(bf2pk(sg0, sg1), bf2pk(sg2, sg3));
    *(uint2*)(sgl + o) = make_uint2(bf2pk(lo_of(sg0), lo_of(sg1)), bf2pk(lo_of(sg2), lo_of(sg3)));
}

// Per-node neighbor-message sum. 64 thr/node, loads hoisted (MLP 10).
__global__ void k_gnode(const int* __restrict__ ng,
                        const __nv_bfloat16* __restrict__ rec,
                        __nv_bfloat16* __restrict__ mnh, __nv_bfloat16* __restrict__ mnl) {
    int gt = blockIdx.x * blockDim.x + threadIdx.x;
    int n = gt >> 6;
    int j = gt & 63;
    if (n >= NNODE) return;
    int gi[5];
#pragma unroll
    for (int k = 0; k < 5; k++) gi[k] = __ldg(ng + n * 5 + k);
    uint2 hh[5], hl[5];
#pragma unroll
    for (int k = 0; k < 5; k++) {
        const __nv_bfloat16* rp = rec + (size_t)gi[k] * 768 + j * 4;
        hh[k] = *(const uint2*)(rp);
        hl[k] = *(const uint2*)(rp + 256);
    }
    float x = 0, y = 0, z = 0, w = 0;
#pragma unroll
    for (int k = 0; k < 5; k++) {
        x += bf_lo16(hh[k].x) + bf_lo16(hl[k].x);
        y += bf_hi16(hh[k].x) + bf_hi16(hl[k].x);
        z += bf_lo16(hh[k].y) + bf_lo16(hl[k].y);
        w += bf_hi16(hh[k].y) + bf_hi16(hl[k].y);
    }
    size_t o = (size_t)n * 256 + j * 4;
    *(uint2*)(mnh + o) = make_uint2(bf2pk(x, y), bf2pk(z, w));
    *(uint2*)(mnl + o) = make_uint2(bf2pk(lo_of(x), lo_of(y)), bf2pk(lo_of(z), lo_of(w)));
}

// Deterministic segment mean over sorted scope_ids.
__global__ void k_seg(const int* __restrict__ scope, const float* __restrict__ nv,
                      float* __restrict__ out) {
    int t = blockIdx.x;
    int j = threadIdx.x;
    int lo = 0, hi = NNODE;
    while (lo < hi) { int mid = (lo + hi) >> 1; if (scope[mid] < t) lo = mid + 1; else hi = mid; }
    int lo2 = lo, hi2 = NNODE;
    while (lo2 < hi2) { int mid = (lo2 + hi2) >> 1; if (scope[mid] < t + 1) lo2 = mid + 1; else hi2 = mid; }
    float s = 0.f;
    for (int r = lo; r < lo2; r++) s += nv[(size_t)r * HID + j];
    out[(size_t)t * HID + j] = s / fmaxf((float)(lo2 - lo), 1.f);
}

// ---------------- persistent tcgen05 GEMM, 128x256 tile ---------------------
// A = bf16 hi/lo planes (row stride lda elements). All staging via cp.async.
// Single fp32 accumulator D (256 TMEM cols), ping-pong per tile (0 / 256).
// Per K64 chunk: 12 MMAs. Deferred epilogue overlaps next tile's MMAs.
//   MODE 0 (U):  rec[m][512+col] = bf16(v)
//   MODE 1 (Z):  zu = u16(sigmoid(EXz[mx[m]] + v) * 65535)
//   MODE 2 (H):  h = (1-z)*sum_h + z*tanh(EXh[mx[m]] + v); mask row0;
//                write rec h planes (hi @ col, lo @ 256+col)
//   MODE 3 (NV): nv = relu(EO[fn[m]] + v)
struct TG {
    const __nv_bfloat16 *Ah, *Al; int lda;
    const __nv_bfloat16 *Bh, *Bl;      // [256][256]
    __nv_bfloat16* rec;                // MODE 0 / MODE 2 out
    unsigned short* zu;                // MODE 1 out / MODE 2 in
    const float* EX; const int* mx;    // MODE 1,2
    const __nv_bfloat16 *shh, *shl;    // MODE 2 in
    const float* EO; const int* fn; float* nv;  // MODE 3
    int mT;
};

#if TC_OK
template <int MODE>
__device__ __forceinline__ void epi(const TG& p, uint32_t dbase, int m0, int tid) {
    int w = tid >> 5, l = tid & 31;
    int row = (w & 3) * 32 + l;
    int m = m0 + row;
    int chl = (w >> 2) * 128;
    int mxm = 0;
    if (MODE == 1 || MODE == 2) mxm = __ldg(p.mx + m);
    if (MODE == 3) mxm = __ldg(p.fn + m);
#pragma unroll 1
    for (int cb = 0; cb < 4; cb++) {
        int col = chl + cb * 32;
        uint32_t rr[32];
        tmem_ld32(rr, dbase + col);
        TC_WAIT_LD();
        float v[32];
#pragma unroll
        for (int i = 0; i < 32; i++) v[i] = __uint_as_float(rr[i]);
        if (MODE == 0) {
            uint4* dst = (uint4*)(p.rec + (size_t)m * 768 + 512 + col);
#pragma unroll
            for (int i2 = 0; i2 < 4; i2++)
                dst[i2] = make_uint4(bf2pk(v[i2*8+0], v[i2*8+1]), bf2pk(v[i2*8+2], v[i2*8+3]),
                                     bf2pk(v[i2*8+4], v[i2*8+5]), bf2pk(v[i2*8+6], v[i2*8+7]));
        } else if (MODE == 1) {
            const float4* ex4 = (const float4*)(p.EX + (size_t)mxm * 768 + col);
            uint32_t zp[16];
#pragma unroll
            for (int j2 = 0; j2 < 8; j2++) {
                float4 ex = ex4[j2];
                uint32_t a = __float2uint_rn(sgm(ex.x + v[j2*4+0]) * 65535.f);
                uint32_t b = __float2uint_rn(sgm(ex.y + v[j2*4+1]) * 65535.f);
                uint32_t c = __float2uint_rn(sgm(ex.z + v[j2*4+2]) * 65535.f);
                uint32_t d = __float2uint_rn(sgm(ex.w + v[j2*4+3]) * 65535.f);
                zp[j2*2+0] = a | (b << 16);
                zp[j2*2+1] = c | (d << 16);
            }
            uint4* dst = (uint4*)(p.zu + (size_t)m * 256 + col);
#pragma unroll
            for (int i2 = 0; i2 < 4; i2++)
                dst[i2] = make_uint4(zp[i2*4+0], zp[i2*4+1], zp[i2*4+2], zp[i2*4+3]);
        } else if (MODE == 2) {
            const float4* xh4 = (const float4*)(p.EX + (size_t)mxm * 768 + 256 + col);
            const uint4* shh4 = (const uint4*)(p.shh + (size_t)m * 256 + col);
            const uint4* shl4 = (const uint4*)(p.shl + (size_t)m * 256 + col);
            const uint4* zp4 = (const uint4*)(p.zu + (size_t)m * 256 + col);
            uint4* hdh = (uint4*)(p.rec + (size_t)m * 768 + col);
            uint4* hdl = (uint4*)(p.rec + (size_t)m * 768 + 256 + col);
            const float inv = 1.f / 65535.f;
#pragma unroll
            for (int j2 = 0; j2 < 4; j2++) {     // 8-col groups
                float4 xa = xh4[j2 * 2], xb = xh4[j2 * 2 + 1];
                uint4 sh = shh4[j2], sl = shl4[j2], zz = zp4[j2];
                float xh[8] = {xa.x, xa.y, xa.z, xa.w, xb.x, xb.y, xb.z, xb.w};
                float su[8] = {bf_lo16(sh.x) + bf_lo16(sl.x), bf_hi16(sh.x) + bf_hi16(sl.x),
                               bf_lo16(sh.y) + bf_lo16(sl.y), bf_hi16(sh.y) + bf_hi16(sl.y),
                               bf_lo16(sh.z) + bf_lo16(sl.z), bf_hi16(sh.z) + bf_hi16(sl.z),
                               bf_lo16(sh.w) + bf_lo16(sl.w), bf_hi16(sh.w) + bf_hi16(sl.w)};
                uint32_t zw[4] = {zz.x, zz.y, zz.z, zz.w};
                float h[8];
#pragma unroll
                for (int i = 0; i < 8; i++) {
                    float z = (float)((zw[i >> 1] >> ((i & 1) * 16)) & 0xFFFF) * inv;
                    h[i] = (1.f - z) * su[i] + z * tanhf(xh[i] + v[j2 * 8 + i]);
                    if (m == 0) h[i] = 0.f;
                }
                hdh[j2] = make_uint4(bf2pk(h[0], h[1]), bf2pk(h[2], h[3]),
                                     bf2pk(h[4], h[5]), bf2pk(h[6], h[7]));
                hdl[j2] = make_uint4(bf2pk(lo_of(h[0]), lo_of(h[1])), bf2pk(lo_of(h[2]), lo_of(h[3])),
                                     bf2pk(lo_of(h[4]), lo_of(h[5])), bf2pk(lo_of(h[6]), lo_of(h[7])));
            }
        } else {
            const float4* eo4 = (const float4*)(p.EO + (size_t)mxm * 256 + col);
            float4* dst = (float4*)(p.nv + (size_t)m * 256 + col);
#pragma unroll
            for (int j2 = 0; j2 < 8; j2++) {
                float4 eo = eo4[j2];
                dst[j2] = make_float4(fmaxf(eo.x + v[j2*4+0], 0.f),
                                      fmaxf(eo.y + v[j2*4+1], 0.f),
                                      fmaxf(eo.z + v[j2*4+2], 0.f),
                                      fmaxf(eo.w + v[j2*4+3], 0.f));
            }
        }
    }
    TC_FENCE_BEFORE();
}
#endif

template <int MODE>
__global__ void __launch_bounds__(256) tgemm(TG p) {
    extern __shared__ char smraw[];
    char* sm = (char*)(((uintptr_t)smraw + 1023) & ~(uintptr_t)1023);
    const int tid = threadIdx.x;
#if TC_OK
    uint32_t sb = su32(sm);
    if (tid < 32) tc_alloc(sb + OFF_PTR, 512);
    if (tid == 0) {
        mbar_init(sb + OFF_MB + 0, 1);  mbar_init(sb + OFF_MB + 8, 1);
        mbar_init(sb + OFF_MB + 16, 1); mbar_init(sb + OFF_MB + 24, 1);
    }
    __syncthreads();
    uint32_t tmem = *(const uint32_t*)(sm + OFF_PTR);

    const int q = tid & 7, r8 = tid >> 3;

    int ph0 = 0, ph1 = 0, pend0 = 0, pend1 = 0;
    int tp0 = 0, tp1 = 0;
    int prev_m0 = -1, prev_db = 0;
    int lc = 0;

    for (int ti = blockIdx.x; ti < p.mT; ti += gridDim.x, lc++) {
        int m0 = ti * 128;
        int db = lc & 1;
        for (int c = 0; c < 4; c++) {
            int s = c & 1;
            if (s == 0) { if (pend0) { mbar_wait(sb + OFF_MB + 0, ph0); ph0 ^= 1; pend0 = 0; } }
            else        { if (pend1) { mbar_wait(sb + OFF_MB + 8, ph1); ph1 ^= 1; pend1 = 0; } }
            {
                const __nv_bfloat16* Ah = p.Ah + (size_t)m0 * p.lda + c * 64 + q * 8;
                const __nv_bfloat16* Al = p.Al + (size_t)m0 * p.lda + c * 64 + q * 8;
#pragma unroll
                for (int u = 0; u < 4; u++) {
                    int row = u * 32 + r8;
                    uint32_t sw = SWZ((uint32_t)(row * 128 + q * 16));
                    cp16(sb + OFF_AH(s) + sw, Ah + (size_t)row * p.lda);
                    cp16(sb + OFF_AL(s) + sw, Al + (size_t)row * p.lda);
                }
            }
            {
                const __nv_bfloat16* Bh = p.Bh + c * 64 + q * 8;
                const __nv_bfloat16* Bl = p.Bl + c * 64 + q * 8;
#pragma unroll
                for (int u = 0; u < 8; u++) {
                    int row = u * 32 + r8;
                    uint32_t sw = SWZ((uint32_t)(row * 128 + q * 16));
                    cp16(sb + OFF_BH(s) + sw, Bh + (size_t)row * 256);
                    cp16(sb + OFF_BL(s) + sw, Bl + (size_t)row * 256);
                }
            }
            CP_COMMIT();
            if (c >= 1) {
                CP_WAIT(1);
                __syncthreads();
                FENCE_ASYNC();
                int sp = s ^ 1;
                if (tid < 32 && elect1()) {
                    uint64_t ah = mk_desc(sb + OFF_AH(sp));
                    uint64_t al = mk_desc(sb + OFF_AL(sp));
                    uint64_t bh = mk_desc(sb + OFF_BH(sp));
                    uint64_t bl = mk_desc(sb + OFF_BL(sp));
                    uint32_t d = tmem + db * 256;
#pragma unroll
                    for (int k = 0; k < 4; k++) {
                        bool acc = (c > 1) || (k > 0);
                        mma_f16_ss(d, ah + k * 2, bh + k * 2, IDESC, acc);
                        mma_f16_ss(d, al + k * 2, bh + k * 2, IDESC, true);
                        mma_f16_ss(d, ah + k * 2, bl + k * 2, IDESC, true);
                    }
                    tc_commit(sb + OFF_MB + sp * 8);
                }
                if (sp) pend1 = 1; else pend0 = 1;
            }
        }
        CP_WAIT(0);
        __syncthreads();
        FENCE_ASYNC();
        if (tid < 32 && elect1()) {
            uint64_t ah = mk_desc(sb + OFF_AH(1));
            uint64_t al = mk_desc(sb + OFF_AL(1));
            uint64_t bh = mk_desc(sb + OFF_BH(1));
            uint64_t bl = mk_desc(sb + OFF_BL(1));
            uint32_t d = tmem + db * 256;
#pragma unroll
            for (int k = 0; k < 4; k++) {
                mma_f16_ss(d, ah + k * 2, bh + k * 2, IDESC, true);
                mma_f16_ss(d, al + k * 2, bh + k * 2, IDESC, true);
                mma_f16_ss(d, ah + k * 2, bl + k * 2, IDESC, true);
            }
            tc_commit(sb + OFF_MB + 8);
            tc_commit(sb + OFF_MB + 16 + db * 8);
        }
        pend1 = 1;
        if (prev_m0 >= 0) {
            if (prev_db == 0) { mbar_wait(sb + OFF_MB + 16, tp0); tp0 ^= 1; }
            else              { mbar_wait(sb + OFF_MB + 24, tp1); tp1 ^= 1; }
            TC_FENCE_AFTER();
            epi<MODE>(p, tmem + prev_db * 256, prev_m0, tid);
        }
        prev_m0 = m0; prev_db = db;
    }
    if (prev_m0 >= 0) {
        if (prev_db == 0) { mbar_wait(sb + OFF_MB + 16, tp0); tp0 ^= 1; }
        else              { mbar_wait(sb + OFF_MB + 24, tp1); tp1 ^= 1; }
        TC_FENCE_AFTER();
        epi<MODE>(p, tmem + prev_db * 256, prev_m0, tid);
    }
    __syncthreads();
    if (tid < 32) tc_dealloc(tmem, 512);
#else
    for (int ti = blockIdx.x; ti < p.mT; ti += gridDim.x) {
        int m0 = ti * 128;
        for (int e = tid; e < 128 * 256; e += 256) {
            int r = e >> 8, col = e & 255;
            int m = m0 + r;
            float acc = 0.f;
            for (int k = 0; k < 256; k++) {
                float a = __bfloat162float(p.Ah[(size_t)m * p.lda + k])
                        + __bfloat162float(p.Al[(size_t)m * p.lda + k]);
                float b = __bfloat162float(p.Bh[(size_t)col * 256 + k])
                        + __bfloat162float(p.Bl[(size_t)col * 256 + k]);
                acc += a * b;
            }
            if (MODE == 0) {
                p.rec[(size_t)m * 768 + 512 + col] = __float2bfloat16(acc);
            } else if (MODE == 1) {
                int mxm = p.mx[m];
                float z = sgm(p.EX[(size_t)mxm * 768 + col] + acc);
                p.zu[(size_t)m * 256 + col] =
                    (unsigned short)__float2uint_rn(z * 65535.f);
            } else if (MODE == 2) {
                int mxm = p.mx[m];
                float z = (float)p.zu[(size_t)m * 256 + col] * (1.f / 65535.f);
                float sh = __bfloat162float(p.shh[(size_t)m * 256 + col])
                         + __bfloat162float(p.shl[(size_t)m * 256 + col]);
                float h = (1.f - z) * sh
                        + z * tanhf(p.EX[(size_t)mxm * 768 + 256 + col] + acc);
                if (m == 0) h = 0.f;
                __nv_bfloat16 hb = __float2bfloat16(h);
                p.rec[(size_t)m * 768 + col] = hb;
                p.rec[(size_t)m * 768 + 256 + col] =
                    __float2bfloat16(h - __bfloat162float(hb));
            } else {
                int fn = p.fn[m];
                p.nv[(size_t)m * 256 + col] =
                    fmaxf(p.EO[(size_t)fn * 256 + col] + acc, 0.f);
            }
        }
    }
#endif
}

// ---------------- orchestration --------------------------------------------
extern "C" void kernel_launch(void* const* d_in, const int* in_sizes, int n_in,
                              void* d_out, int out_size) {
    const int*   fnode = (const int*)d_in[0];
    const int*   fmess = (const int*)d_in[1];
    const int*   ng    = (const int*)d_in[2];
    const int*   mg    = (const int*)d_in[3];
    const int*   scope = (const int*)d_in[4];
    const float* emb   = (const float*)d_in[5];
    const float* Wz    = (const float*)d_in[6];
    const float* Wzb   = (const float*)d_in[7];
    const float* Wr    = (const float*)d_in[8];
    const float* Ur    = (const float*)d_in[9];
    const float* Urb   = (const float*)d_in[10];
    const float* Wh    = (const float*)d_in[11];
    const float* Whb   = (const float*)d_in[12];
    const float* Ow    = (const float*)d_in[13];
    const float* Ob    = (const float*)d_in[14];
    float* out = (float*)d_out;

    __nv_bfloat16 *rec, *shh, *shl, *sgh, *sgl, *mnh, *mnl;
    __nv_bfloat16 *BUh, *BUl, *BZh, *BZl, *BHh, *BHl, *BOh, *BOl;
    unsigned short* zu;
    float *nv, *EX, *EO;
    int* mx;
    cudaGetSymbolAddress((void**)&rec, g_rec);
    cudaGetSymbolAddress((void**)&shh, g_shh); cudaGetSymbolAddress((void**)&shl, g_shl);
    cudaGetSymbolAddress((void**)&sgh, g_sgh); cudaGetSymbolAddress((void**)&sgl, g_sgl);
    cudaGetSymbolAddress((void**)&mnh, g_mnh); cudaGetSymbolAddress((void**)&mnl, g_mnl);
    cudaGetSymbolAddress((void**)&zu,  g_zu);
    cudaGetSymbolAddress((void**)&nv,  g_nv);
    cudaGetSymbolAddress((void**)&EX,  g_EX);
    cudaGetSymbolAddress((void**)&EO,  g_EO);
    cudaGetSymbolAddress((void**)&mx,  g_mx);
    cudaGetSymbolAddress((void**)&BUh, g_BUh); cudaGetSymbolAddress((void**)&BUl, g_BUl);
    cudaGetSymbolAddress((void**)&BZh, g_BZh); cudaGetSymbolAddress((void**)&BZl, g_BZl);
    cudaGetSymbolAddress((void**)&BHh, g_BHh); cudaGetSymbolAddress((void**)&BHl, g_BHl);
    cudaGetSymbolAddress((void**)&BOh, g_BOh); cudaGetSymbolAddress((void**)&BOl, g_BOl);

    cudaFuncSetAttribute(tgemm<0>, cudaFuncAttributeMaxDynamicSharedMemorySize, TG_SMEM);
    cudaFuncSetAttribute(tgemm<1>, cudaFuncAttributeMaxDynamicSharedMemorySize, TG_SMEM);
    cudaFuncSetAttribute(tgemm<2>, cudaFuncAttributeMaxDynamicSharedMemorySize, TG_SMEM);
    cudaFuncSetAttribute(tgemm<3>, cudaFuncAttributeMaxDynamicSharedMemorySize, TG_SMEM);

    size_t recw = (size_t)M_MSG * 768 * 2 / 4;
    k_zero<<<(unsigned)((recw + 255) / 256), 256>>>((uint32_t*)rec, recw);
    k_pack<<<512, 256>>>(Wz, Wh, Ur, Ow, fnode, fmess, mx);
    k_prep<<<780, 256>>>(emb, Wz, Wh, Wr, Ow, Wzb, Whb, Urb, Ob, EX, EO);

    for (int d = 0; d < DEPTH; d++) {
        // U = h @ Ur  -> rec[:,512:768]
        TG pU{}; pU.Ah = rec; pU.Al = rec + 256; pU.lda = 768;
        pU.Bh = BUh; pU.Bl = BUl; pU.rec = rec; pU.mT = M_MSG / 128;
        tgemm<0><<<GRID_P, 256, TG_SMEM>>>(pU);
        // gather: sum_h, sum_gh
        k_gather<<<(M_MSG * 64) / 256, 256>>>(mg, rec, EX, mx, shh, shl, sgh, sgl);
        // z = sigmoid(EXz[mx] + sum_h @ Wzh)
        TG pZ{}; pZ.Ah = shh; pZ.Al = shl; pZ.lda = 256;
        pZ.Bh = BZh; pZ.Bl = BZl; pZ.zu = zu; pZ.EX = EX; pZ.mx = mx;
        pZ.mT = M_MSG / 128;
        tgemm<1><<<GRID_P, 256, TG_SMEM>>>(pZ);
        // h = (1-z)*sum_h + z*tanh(EXh[mx] + sum_gh @ Whh) -> rec h planes
        TG pH{}; pH.Ah = sgh; pH.Al = sgl; pH.lda = 256;
        pH.Bh = BHh; pH.Bl = BHl; pH.rec = rec; pH.zu = zu;
        pH.EX = EX; pH.mx = mx; pH.shh = shh; pH.shl = shl;
        pH.mT = M_MSG / 128;
        tgemm<2><<<GRID_P, 256, TG_SMEM>>>(pH);
    }

    // mess_nei per node
    k_gnode<<<(NNODE * 64) / 256, 256>>>(ng, rec, mnh, mnl);

    // node_vec = relu(EO[fnode] + mn @ Ow2)
    TG pN{}; pN.Ah = mnh; pN.Al = mnl; pN.lda = 256;
    pN.Bh = BOh; pN.Bl = BOl; pN.EO = EO; pN.fn = fnode; pN.nv = nv;
    pN.mT = NNODE / 128;
    tgemm<3><<<GRID_P, 256, TG_SMEM>>>(pN);

    // segment mean (sorted scopes, deterministic)
    k_seg<<<NTREE, 256>>>(scope, nv, out);
}

// round 15
// speedup vs baseline: 1.2460x; 1.0125x over previous
#include <cuda_runtime.h>
#include <cuda_bf16.h>
#include <cstdint>
#include <cstddef>

#define M_MSG 131072
#define NNODE 65536
#define HID   256
#define DEPTH 6
#define NTREE 2048
#define GRID_P 148

#if defined(__CUDA_ARCH_FEAT_SM103_ALL) || defined(__CUDA_ARCH_FEAT_SM100_ALL) || \
    defined(__CUDA_ARCH_FEAT_SM101_ALL) || defined(__CUDA_ARCH_FEAT_SM110_ALL)
#define TC_OK 1
#else
#define TC_OK 0
#endif

// ---------------- static device scratch ------------------------------------
// Per-message record: [0:256) h_hi | [256:512) h_lo | [512:768) U   (bf16)
__device__ __nv_bfloat16 g_rec[(size_t)M_MSG * 768];
// GEMM A operands as bf16 hi/lo planes
__device__ __nv_bfloat16 g_shh[(size_t)M_MSG * 256], g_shl[(size_t)M_MSG * 256]; // sum_h
__device__ __nv_bfloat16 g_sgh[(size_t)M_MSG * 256], g_sgl[(size_t)M_MSG * 256]; // sum_gh
__device__ __nv_bfloat16 g_mnh[(size_t)NNODE * 256], g_mnl[(size_t)NNODE * 256]; // mess_nei
__device__ unsigned short g_zu[(size_t)M_MSG * 256];  // z gate u16 fixed point
__device__ float g_nv[(size_t)NNODE * 256];           // node_vec
__device__ float g_EX[780 * 768];                     // emb@[Wzx|Whx|Wr]+biases
__device__ float g_EO[780 * 256];                     // emb@Ow1+Ob
__device__ int   g_mx[M_MSG];                         // fnode[fmess[m]]
// bf16 hi/lo split weights, [n][k] layout (B operand = W^T), all 256x256
__device__ __nv_bfloat16 g_BUh[256 * 256], g_BUl[256 * 256];  // Ur^T
__device__ __nv_bfloat16 g_BZh[256 * 256], g_BZl[256 * 256];  // Wzh^T
__device__ __nv_bfloat16 g_BHh[256 * 256], g_BHl[256 * 256];  // Whh^T
__device__ __nv_bfloat16 g_BOh[256 * 256], g_BOl[256 * 256];  // Ow2^T

// ---------------- bf16 helpers ----------------------------------------------
__device__ __forceinline__ float bf_lo16(uint32_t u) { return __uint_as_float(u << 16); }
__device__ __forceinline__ float bf_hi16(uint32_t u) { return __uint_as_float(u & 0xFFFF0000u); }
__device__ __forceinline__ uint32_t bf2pk(float a, float b) {
    return (uint32_t)__bfloat16_as_ushort(__float2bfloat16(a))
         | ((uint32_t)__bfloat16_as_ushort(__float2bfloat16(b)) << 16);
}
__device__ __forceinline__ float lo_of(float v) {
    return v - __bfloat162float(__float2bfloat16(v));
}
__device__ __forceinline__ float sgm(float x) { return 1.0f / (1.0f + __expf(-x)); }
// streaming store (evict-first; keeps gather's rec rows resident in L2)
__device__ __forceinline__ void stcs2(void* p, uint2 v) {
    asm volatile("st.global.cs.v2.u32 [%0], {%1,%2};"
                 :: "l"(p), "r"(v.x), "r"(v.y) : "memory");
}

// ---------------- PTX helpers ------------------------------------------------
__device__ __forceinline__ uint32_t su32(const void* p) {
    uint32_t a;
    asm("{ .reg .u64 t; cvta.to.shared.u64 t, %1; cvt.u32.u64 %0, t; }"
        : "=r"(a) : "l"(p));
    return a;
}
#if TC_OK
__device__ __forceinline__ bool elect1() {
    uint32_t p;
    asm volatile("{\n\t.reg .pred p;\n\telect.sync _|p, 0xFFFFFFFF;\n\t"
                 "selp.b32 %0, 1, 0, p;\n\t}" : "=r"(p));
    return p != 0;
}
__device__ __forceinline__ void mbar_init(uint32_t a, uint32_t cnt) {
    asm volatile("mbarrier.init.shared.b64 [%0], %1;" :: "r"(a), "r"(cnt) : "memory");
}
__device__ __forceinline__ void mbar_wait(uint32_t a, int par) {
    asm volatile(
        "{\n\t.reg .pred P;\n"
        "W%=:\n\t"
        "mbarrier.try_wait.parity.acquire.cta.shared::cta.b64 P, [%0], %1, 0x989680;\n\t"
        "@P bra.uni D%=;\n\t"
        "bra.uni W%=;\n"
        "D%=:\n\t}" :: "r"(a), "r"(par) : "memory");
}
__device__ __forceinline__ void tc_alloc(uint32_t smem_res, uint32_t ncols) {
    asm volatile("tcgen05.alloc.cta_group::1.sync.aligned.shared::cta.b32 [%0], %1;"
                 :: "r"(smem_res), "r"(ncols) : "memory");
}
__device__ __forceinline__ void tc_dealloc(uint32_t tmem, uint32_t ncols) {
    asm volatile("tcgen05.dealloc.cta_group::1.sync.aligned.b32 %0, %1;"
                 :: "r"(tmem), "r"(ncols));
}
__device__ __forceinline__ void tc_commit(uint32_t mbar) {
    asm volatile("tcgen05.commit.cta_group::1.mbarrier::arrive::one.shared::cluster.b64 [%0];"
                 :: "r"(mbar) : "memory");
}
__device__ __forceinline__ void mma_f16_ss(uint32_t d, uint64_t ad, uint64_t bd,
                                           uint32_t idesc, bool acc) {
    uint32_t en = acc ? 1u : 0u;
    asm volatile(
        "{\n\t.reg .pred p;\n\tsetp.ne.u32 p, %5, 0;\n\t"
        "tcgen05.mma.cta_group::1.kind::f16 [%0], %1, %2, %3, {%4, %4, %4, %4}, p;\n\t}"
        :: "r"(d), "l"(ad), "l"(bd), "r"(idesc), "r"(0u), "r"(en) : "memory");
}
__device__ __forceinline__ void tmem_ld32(uint32_t* r, uint32_t addr) {
    asm volatile(
        "tcgen05.ld.sync.aligned.32x32b.x32.b32 "
        "{%0,%1,%2,%3,%4,%5,%6,%7,%8,%9,%10,%11,%12,%13,%14,%15,"
        "%16,%17,%18,%19,%20,%21,%22,%23,%24,%25,%26,%27,%28,%29,%30,%31}, [%32];"
        : "=r"(r[0]), "=r"(r[1]), "=r"(r[2]), "=r"(r[3]),
          "=r"(r[4]), "=r"(r[5]), "=r"(r[6]), "=r"(r[7]),
          "=r"(r[8]), "=r"(r[9]), "=r"(r[10]), "=r"(r[11]),
          "=r"(r[12]), "=r"(r[13]), "=r"(r[14]), "=r"(r[15]),
          "=r"(r[16]), "=r"(r[17]), "=r"(r[18]), "=r"(r[19]),
          "=r"(r[20]), "=r"(r[21]), "=r"(r[22]), "=r"(r[23]),
          "=r"(r[24]), "=r"(r[25]), "=r"(r[26]), "=r"(r[27]),
          "=r"(r[28]), "=r"(r[29]), "=r"(r[30]), "=r"(r[31])
        : "r"(addr));
}
__device__ __forceinline__ void cp16(uint32_t dst, const void* src) {
    asm volatile("cp.async.cg.shared.global [%0], [%1], 16;"
                 :: "r"(dst), "l"(src) : "memory");
}
#define CP_COMMIT()      asm volatile("cp.async.commit_group;" ::: "memory")
#define CP_WAIT(n)       asm volatile("cp.async.wait_group %0;" :: "n"(n) : "memory")
#define TC_WAIT_LD()      asm volatile("tcgen05.wait::ld.sync.aligned;" ::: "memory")
#define TC_FENCE_AFTER()  asm volatile("tcgen05.fence::after_thread_sync;" ::: "memory")
#define TC_FENCE_BEFORE() asm volatile("tcgen05.fence::before_thread_sync;" ::: "memory")
#define FENCE_ASYNC()     asm volatile("fence.proxy.async.shared::cta;" ::: "memory")
#endif  // TC_OK

#define SWZ(o) ((o) ^ (((o) >> 3) & 0x70))

__device__ __forceinline__ uint64_t mk_desc(uint32_t addr) {
    return (2ull << 61) | (1ull << 46) | (64ull << 32) | (1ull << 16)
         | ((uint64_t)(addr >> 4) & 0x3FFF);
}

// idesc: dtype=F32, a=BF16, b=BF16, N=256, M=128
static constexpr uint32_t IDESC =
    (1u << 4) | (1u << 7) | (1u << 10) | ((256u / 8) << 17) | ((128u / 16) << 24);

// SMEM layout (bytes from 1024-aligned base)
#define OFF_PTR   0
#define OFF_MB    16          // chunk mbars @16,24; tile mbars @32,40
#define OFF_AH(s) (1024 + (s) * 32768)
#define OFF_AL(s) (1024 + (s) * 32768 + 16384)
#define OFF_BH(s) (66560 + (s) * 65536)
#define OFF_BL(s) (66560 + (s) * 65536 + 32768)
#define TG_SMEM   198656

// ---------------- small kernels ---------------------------------------------
__global__ void k_zero(uint32_t* p, size_t n) {
    size_t i = (size_t)blockIdx.x * blockDim.x + threadIdx.x;
    if (i < n) p[i] = 0u;
}

__device__ __forceinline__ void bsplit(float w, __nv_bfloat16* H, __nv_bfloat16* L, int i) {
    __nv_bfloat16 h = __float2bfloat16(w);
    H[i] = h;
    L[i] = __float2bfloat16(w - __bfloat162float(h));
}

__global__ void k_pack(const float* __restrict__ Wz, const float* __restrict__ Wh,
                       const float* __restrict__ Ur, const float* __restrict__ Ow,
                       const int* __restrict__ fnode, const int* __restrict__ fmess,
                       int* __restrict__ mx) {
    int i = blockIdx.x * blockDim.x + threadIdx.x;
    int st = gridDim.x * blockDim.x;
    for (int t = i; t < 256 * 256; t += st) {
        int n = t >> 8, k = t & 255;
        bsplit(Ur[k * 256 + n],         g_BUh, g_BUl, t);
        bsplit(Wz[(256 + k) * 256 + n], g_BZh, g_BZl, t);
        bsplit(Wh[(256 + k) * 256 + n], g_BHh, g_BHl, t);
        bsplit(Ow[(256 + k) * 256 + n], g_BOh, g_BOl, t);
    }
    for (int t = i; t < M_MSG; t += st) mx[t] = fnode[fmess[t]];
}

// EX/EO tables: per-vocab precompute of all x-dependent matmuls.
__global__ void k_prep(const float* __restrict__ emb,
                       const float* __restrict__ Wz, const float* __restrict__ Wh,
                       const float* __restrict__ Wr, const float* __restrict__ Ow,
                       const float* __restrict__ Wzb, const float* __restrict__ Whb,
                       const float* __restrict__ Urb, const float* __restrict__ Ob,
                       float* __restrict__ EX, float* __restrict__ EO) {
    __shared__ float e[256];
    int v = blockIdx.x, j = threadIdx.x;
    e[j] = emb[v * 256 + j];
    __syncthreads();
    float s0 = 0, s1 = 0, s2 = 0, s3 = 0;
#pragma unroll 4
    for (int k = 0; k < 256; k++) {
        float ek = e[k];
        s0 = fmaf(ek, Wz[k * 256 + j], s0);
        s1 = fmaf(ek, Wh[k * 256 + j], s1);
        s2 = fmaf(ek, Wr[k * 256 + j], s2);
        s3 = fmaf(ek, Ow[k * 256 + j], s3);
    }
    EX[v * 768 + j]       = s0 + Wzb[j];
    EX[v * 768 + 256 + j] = s1 + Whb[j];
    EX[v * 768 + 512 + j] = s2 + Urb[j];
    EO[v * 256 + j]       = s3 + Ob[j];
}

// Gather pass over a 128-column half (cb = 0 or 128). 32 thr/msg, 4 cols each.
// Unique rec bytes touched per pass: 3 planes x 128 cols x 2B x 128K = 98 MB
// -> fits L2 (126 MB), so the 5x neighbor reuse becomes L2 hits. Outputs are
// streamed (st.global.cs) to avoid evicting the rec rows.
__global__ void k_gather(const int* __restrict__ mg,
                         const __nv_bfloat16* __restrict__ rec,
                         const float* __restrict__ EX, const int* __restrict__ mx,
                         __nv_bfloat16* __restrict__ shh, __nv_bfloat16* __restrict__ shl,
                         __nv_bfloat16* __restrict__ sgh, __nv_bfloat16* __restrict__ sgl,
                         int cb) {
    int gt = blockIdx.x * blockDim.x + threadIdx.x;
    int msg = gt >> 5;
    int j = gt & 31;
    if (msg >= M_MSG) return;
    int col = cb + j * 4;
    int mxv = __ldg(mx + msg);
    int gi[5];
#pragma unroll
    for (int k = 0; k < 5; k++) gi[k] = __ldg(mg + msg * 5 + k);
    // issue all neighbor loads up front
    uint2 hh[5], hl[5], uu[5];
#pragma unroll
    for (int k = 0; k < 5; k++) {
        const __nv_bfloat16* rp = rec + (size_t)gi[k] * 768 + col;
        hh[k] = *(const uint2*)(rp);
        hl[k] = *(const uint2*)(rp + 256);
        uu[k] = *(const uint2*)(rp + 512);
    }
    float4 r1 = *(const float4*)(EX + (size_t)mxv * 768 + 512 + col);
    float sh0 = 0, sh1 = 0, sh2 = 0, sh3 = 0;
    float sg0 = 0, sg1 = 0, sg2 = 0, sg3 = 0;
#pragma unroll
    for (int k = 0; k < 5; k++) {
        float h0 = bf_lo16(hh[k].x) + bf_lo16(hl[k].x);
        float h1 = bf_hi16(hh[k].x) + bf_hi16(hl[k].x);
        float h2 = bf_lo16(hh[k].y) + bf_lo16(hl[k].y);
        float h3 = bf_hi16(hh[k].y) + bf_hi16(hl[k].y);
        sh0 += h0; sh1 += h1; sh2 += h2; sh3 += h3;
        sg0 += sgm(r1.x + bf_lo16(uu[k].x)) * h0;
        sg1 += sgm(r1.y + bf_hi16(uu[k].x)) * h1;
        sg2 += sgm(r1.z + bf_lo16(uu[k].y)) * h2;
        sg3 += sgm(r1.w + bf_hi16(uu[k].y)) * h3;
    }
    size_t o = (size_t)msg * 256 + col;
    stcs2(shh + o, make_uint2(bf2pk(sh0, sh1), bf2pk(sh2, sh3)));
    stcs2(shl + o, make_uint2(bf2pk(lo_of(sh0), lo_of(sh1)), bf2pk(lo_of(sh2), lo_of(sh3))));
    stcs2(sgh + o, make_uint2(bf2pk(sg0, sg1), bf2pk(sg2, sg3)));
    stcs2(sgl + o, make_uint2(bf2pk(lo_of(sg0), lo_of(sg1)), bf2pk(lo_of(sg2), lo_of(sg3))));
}

// Per-node neighbor-message sum. 64 thr/node, loads hoisted (MLP 10).
__global__ void k_gnode(const int* __restrict__ ng,
                        const __nv_bfloat16* __restrict__ rec,
                        __nv_bfloat16* __restrict__ mnh, __nv_bfloat16* __restrict__ mnl) {
    int gt = blockIdx.x * blockDim.x + threadIdx.x;
    int n = gt >> 6;
    int j = gt & 63;
    if (n >= NNODE) return;
    int gi[5];
#pragma unroll
    for (int k = 0; k < 5; k++) gi[k] = __ldg(ng + n * 5 + k);
    uint2 hh[5], hl[5];
#pragma unroll
    for (int k = 0; k < 5; k++) {
        const __nv_bfloat16* rp = rec + (size_t)gi[k] * 768 + j * 4;
        hh[k] = *(const uint2*)(rp);
        hl[k] = *(const uint2*)(rp + 256);
    }
    float x = 0, y = 0, z = 0, w = 0;
#pragma unroll
    for (int k = 0; k < 5; k++) {
        x += bf_lo16(hh[k].x) + bf_lo16(hl[k].x);
        y += bf_hi16(hh[k].x) + bf_hi16(hl[k].x);
        z += bf_lo16(hh[k].y) + bf_lo16(hl[k].y);
        w += bf_hi16(hh[k].y) + bf_hi16(hl[k].y);
    }
    size_t o = (size_t)n * 256 + j * 4;
    *(uint2*)(mnh + o) = make_uint2(bf2pk(x, y), bf2pk(z, w));
    *(uint2*)(mnl + o) = make_uint2(bf2pk(lo_of(x), lo_of(y)), bf2pk(lo_of(z), lo_of(w)));
}

// Deterministic segment mean over sorted scope_ids.
__global__ void k_seg(const int* __restrict__ scope, const float* __restrict__ nv,
                      float* __restrict__ out) {
    int t = blockIdx.x;
    int j = threadIdx.x;
    int lo = 0, hi = NNODE;
    while (lo < hi) { int mid = (lo + hi) >> 1; if (scope[mid] < t) lo = mid + 1; else hi = mid; }
    int lo2 = lo, hi2 = NNODE;
    while (lo2 < hi2) { int mid = (lo2 + hi2) >> 1; if (scope[mid] < t + 1) lo2 = mid + 1; else hi2 = mid; }
    float s = 0.f;
    for (int r = lo; r < lo2; r++) s += nv[(size_t)r * HID + j];
    out[(size_t)t * HID + j] = s / fmaxf((float)(lo2 - lo), 1.f);
}

// ---------------- persistent tcgen05 GEMM, 128x256 tile ---------------------
// A = bf16 hi/lo planes (row stride lda elements). All staging via cp.async.
// Single fp32 accumulator D (256 TMEM cols), ping-pong per tile (0 / 256).
// Per K64 chunk: 12 MMAs. Deferred epilogue overlaps next tile's MMAs.
//   MODE 0 (U):  rec[m][512+col] = bf16(v)
//   MODE 1 (Z):  zu = u16(sigmoid(EXz[mx[m]] + v) * 65535)
//   MODE 2 (H):  h = (1-z)*sum_h + z*tanh(EXh[mx[m]] + v); mask row0;
//                write rec h planes (hi @ col, lo @ 256+col)
//   MODE 3 (NV): nv = relu(EO[fn[m]] + v)
struct TG {
    const __nv_bfloat16 *Ah, *Al; int lda;
    const __nv_bfloat16 *Bh, *Bl;      // [256][256]
    __nv_bfloat16* rec;                // MODE 0 / MODE 2 out
    unsigned short* zu;                // MODE 1 out / MODE 2 in
    const float* EX; const int* mx;    // MODE 1,2
    const __nv_bfloat16 *shh, *shl;    // MODE 2 in
    const float* EO; const int* fn; float* nv;  // MODE 3
    int mT;
};

#if TC_OK
template <int MODE>
__device__ __forceinline__ void epi(const TG& p, uint32_t dbase, int m0, int tid) {
    int w = tid >> 5, l = tid & 31;
    int row = (w & 3) * 32 + l;
    int m = m0 + row;
    int chl = (w >> 2) * 128;
    int mxm = 0;
    if (MODE == 1 || MODE == 2) mxm = __ldg(p.mx + m);
    if (MODE == 3) mxm = __ldg(p.fn + m);
#pragma unroll 1
    for (int cb = 0; cb < 4; cb++) {
        int col = chl + cb * 32;
        uint32_t rr[32];
        tmem_ld32(rr, dbase + col);
        TC_WAIT_LD();
        float v[32];
#pragma unroll
        for (int i = 0; i < 32; i++) v[i] = __uint_as_float(rr[i]);
        if (MODE == 0) {
            uint4* dst = (uint4*)(p.rec + (size_t)m * 768 + 512 + col);
#pragma unroll
            for (int i2 = 0; i2 < 4; i2++)
                dst[i2] = make_uint4(bf2pk(v[i2*8+0], v[i2*8+1]), bf2pk(v[i2*8+2], v[i2*8+3]),
                                     bf2pk(v[i2*8+4], v[i2*8+5]), bf2pk(v[i2*8+6], v[i2*8+7]));
        } else if (MODE == 1) {
            const float4* ex4 = (const float4*)(p.EX + (size_t)mxm * 768 + col);
            uint32_t zp[16];
#pragma unroll
            for (int j2 = 0; j2 < 8; j2++) {
                float4 ex = ex4[j2];
                uint32_t a = __float2uint_rn(sgm(ex.x + v[j2*4+0]) * 65535.f);
                uint32_t b = __float2uint_rn(sgm(ex.y + v[j2*4+1]) * 65535.f);
                uint32_t c = __float2uint_rn(sgm(ex.z + v[j2*4+2]) * 65535.f);
                uint32_t d = __float2uint_rn(sgm(ex.w + v[j2*4+3]) * 65535.f);
                zp[j2*2+0] = a | (b << 16);
                zp[j2*2+1] = c | (d << 16);
            }
            uint4* dst = (uint4*)(p.zu + (size_t)m * 256 + col);
#pragma unroll
            for (int i2 = 0; i2 < 4; i2++)
                dst[i2] = make_uint4(zp[i2*4+0], zp[i2*4+1], zp[i2*4+2], zp[i2*4+3]);
        } else if (MODE == 2) {
            const float4* xh4 = (const float4*)(p.EX + (size_t)mxm * 768 + 256 + col);
            const uint4* shh4 = (const uint4*)(p.shh + (size_t)m * 256 + col);
            const uint4* shl4 = (const uint4*)(p.shl + (size_t)m * 256 + col);
            const uint4* zp4 = (const uint4*)(p.zu + (size_t)m * 256 + col);
            uint4* hdh = (uint4*)(p.rec + (size_t)m * 768 + col);
            uint4* hdl = (uint4*)(p.rec + (size_t)m * 768 + 256 + col);
            const float inv = 1.f / 65535.f;
#pragma unroll
            for (int j2 = 0; j2 < 4; j2++) {     // 8-col groups
                float4 xa = xh4[j2 * 2], xb = xh4[j2 * 2 + 1];
                uint4 sh = shh4[j2], sl = shl4[j2], zz = zp4[j2];
                float xh[8] = {xa.x, xa.y, xa.z, xa.w, xb.x, xb.y, xb.z, xb.w};
                float su[8] = {bf_lo16(sh.x) + bf_lo16(sl.x), bf_hi16(sh.x) + bf_hi16(sl.x),
                               bf_lo16(sh.y) + bf_lo16(sl.y), bf_hi16(sh.y) + bf_hi16(sl.y),
                               bf_lo16(sh.z) + bf_lo16(sl.z), bf_hi16(sh.z) + bf_hi16(sl.z),
                               bf_lo16(sh.w) + bf_lo16(sl.w), bf_hi16(sh.w) + bf_hi16(sl.w)};
                uint32_t zw[4] = {zz.x, zz.y, zz.z, zz.w};
                float h[8];
#pragma unroll
                for (int i = 0; i < 8; i++) {
                    float z = (float)((zw[i >> 1] >> ((i & 1) * 16)) & 0xFFFF) * inv;
                    h[i] = (1.f - z) * su[i] + z * tanhf(xh[i] + v[j2 * 8 + i]);
                    if (m == 0) h[i] = 0.f;
                }
                hdh[j2] = make_uint4(bf2pk(h[0], h[1]), bf2pk(h[2], h[3]),
                                     bf2pk(h[4], h[5]), bf2pk(h[6], h[7]));
                hdl[j2] = make_uint4(bf2pk(lo_of(h[0]), lo_of(h[1])), bf2pk(lo_of(h[2]), lo_of(h[3])),
                                     bf2pk(lo_of(h[4]), lo_of(h[5])), bf2pk(lo_of(h[6]), lo_of(h[7])));
            }
        } else {
            const float4* eo4 = (const float4*)(p.EO + (size_t)mxm * 256 + col);
            float4* dst = (float4*)(p.nv + (size_t)m * 256 + col);
#pragma unroll
            for (int j2 = 0; j2 < 8; j2++) {
                float4 eo = eo4[j2];
                dst[j2] = make_float4(fmaxf(eo.x + v[j2*4+0], 0.f),
                                      fmaxf(eo.y + v[j2*4+1], 0.f),
                                      fmaxf(eo.z + v[j2*4+2], 0.f),
                                      fmaxf(eo.w + v[j2*4+3], 0.f));
            }
        }
    }
    TC_FENCE_BEFORE();
}
#endif

template <int MODE>
__global__ void __launch_bounds__(256) tgemm(TG p) {
    extern __shared__ char smraw[];
    char* sm = (char*)(((uintptr_t)smraw + 1023) & ~(uintptr_t)1023);
    const int tid = threadIdx.x;
#if TC_OK
    uint32_t sb = su32(sm);
    if (tid < 32) tc_alloc(sb + OFF_PTR, 512);
    if (tid == 0) {
        mbar_init(sb + OFF_MB + 0, 1);  mbar_init(sb + OFF_MB + 8, 1);
        mbar_init(sb + OFF_MB + 16, 1); mbar_init(sb + OFF_MB + 24, 1);
    }
    __syncthreads();
    uint32_t tmem = *(const uint32_t*)(sm + OFF_PTR);

    const int q = tid & 7, r8 = tid >> 3;

    int ph0 = 0, ph1 = 0, pend0 = 0, pend1 = 0;
    int tp0 = 0, tp1 = 0;
    int prev_m0 = -1, prev_db = 0;
    int lc = 0;

    for (int ti = blockIdx.x; ti < p.mT; ti += gridDim.x, lc++) {
        int m0 = ti * 128;
        int db = lc & 1;
        for (int c = 0; c < 4; c++) {
            int s = c & 1;
            if (s == 0) { if (pend0) { mbar_wait(sb + OFF_MB + 0, ph0); ph0 ^= 1; pend0 = 0; } }
            else        { if (pend1) { mbar_wait(sb + OFF_MB + 8, ph1); ph1 ^= 1; pend1 = 0; } }
            {
                const __nv_bfloat16* Ah = p.Ah + (size_t)m0 * p.lda + c * 64 + q * 8;
                const __nv_bfloat16* Al = p.Al + (size_t)m0 * p.lda + c * 64 + q * 8;
#pragma unroll
                for (int u = 0; u < 4; u++) {
                    int row = u * 32 + r8;
                    uint32_t sw = SWZ((uint32_t)(row * 128 + q * 16));
                    cp16(sb + OFF_AH(s) + sw, Ah + (size_t)row * p.lda);
                    cp16(sb + OFF_AL(s) + sw, Al + (size_t)row * p.lda);
                }
            }
            {
                const __nv_bfloat16* Bh = p.Bh + c * 64 + q * 8;
                const __nv_bfloat16* Bl = p.Bl + c * 64 + q * 8;
#pragma unroll
                for (int u = 0; u < 8; u++) {
                    int row = u * 32 + r8;
                    uint32_t sw = SWZ((uint32_t)(row * 128 + q * 16));
                    cp16(sb + OFF_BH(s) + sw, Bh + (size_t)row * 256);
                    cp16(sb + OFF_BL(s) + sw, Bl + (size_t)row * 256);
                }
            }
            CP_COMMIT();
            if (c >= 1) {
                CP_WAIT(1);
                __syncthreads();
                FENCE_ASYNC();
                int sp = s ^ 1;
                if (tid < 32 && elect1()) {
                    uint64_t ah = mk_desc(sb + OFF_AH(sp));
                    uint64_t al = mk_desc(sb + OFF_AL(sp));
                    uint64_t bh = mk_desc(sb + OFF_BH(sp));
                    uint64_t bl = mk_desc(sb + OFF_BL(sp));
                    uint32_t d = tmem + db * 256;
#pragma unroll
                    for (int k = 0; k < 4; k++) {
                        bool acc = (c > 1) || (k > 0);
                        mma_f16_ss(d, ah + k * 2, bh + k * 2, IDESC, acc);
                        mma_f16_ss(d, al + k * 2, bh + k * 2, IDESC, true);
                        mma_f16_ss(d, ah + k * 2, bl + k * 2, IDESC, true);
                    }
                    tc_commit(sb + OFF_MB + sp * 8);
                }
                if (sp) pend1 = 1; else pend0 = 1;
            }
        }
        CP_WAIT(0);
        __syncthreads();
        FENCE_ASYNC();
        if (tid < 32 && elect1()) {
            uint64_t ah = mk_desc(sb + OFF_AH(1));
            uint64_t al = mk_desc(sb + OFF_AL(1));
            uint64_t bh = mk_desc(sb + OFF_BH(1));
            uint64_t bl = mk_desc(sb + OFF_BL(1));
            uint32_t d = tmem + db * 256;
#pragma unroll
            for (int k = 0; k < 4; k++) {
                mma_f16_ss(d, ah + k * 2, bh + k * 2, IDESC, true);
                mma_f16_ss(d, al + k * 2, bh + k * 2, IDESC, true);
                mma_f16_ss(d, ah + k * 2, bl + k * 2, IDESC, true);
            }
            tc_commit(sb + OFF_MB + 8);
            tc_commit(sb + OFF_MB + 16 + db * 8);
        }
        pend1 = 1;
        if (prev_m0 >= 0) {
            if (prev_db == 0) { mbar_wait(sb + OFF_MB + 16, tp0); tp0 ^= 1; }
            else              { mbar_wait(sb + OFF_MB + 24, tp1); tp1 ^= 1; }
            TC_FENCE_AFTER();
            epi<MODE>(p, tmem + prev_db * 256, prev_m0, tid);
        }
        prev_m0 = m0; prev_db = db;
    }
    if (prev_m0 >= 0) {
        if (prev_db == 0) { mbar_wait(sb + OFF_MB + 16, tp0); tp0 ^= 1; }
        else              { mbar_wait(sb + OFF_MB + 24, tp1); tp1 ^= 1; }
        TC_FENCE_AFTER();
        epi<MODE>(p, tmem + prev_db * 256, prev_m0, tid);
    }
    __syncthreads();
    if (tid < 32) tc_dealloc(tmem, 512);
#else
    for (int ti = blockIdx.x; ti < p.mT; ti += gridDim.x) {
        int m0 = ti * 128;
        for (int e = tid; e < 128 * 256; e += 256) {
            int r = e >> 8, col = e & 255;
            int m = m0 + r;
            float acc = 0.f;
            for (int k = 0; k < 256; k++) {
                float a = __bfloat162float(p.Ah[(size_t)m * p.lda + k])
                        + __bfloat162float(p.Al[(size_t)m * p.lda + k]);
                float b = __bfloat162float(p.Bh[(size_t)col * 256 + k])
                        + __bfloat162float(p.Bl[(size_t)col * 256 + k]);
                acc += a * b;
            }
            if (MODE == 0) {
                p.rec[(size_t)m * 768 + 512 + col] = __float2bfloat16(acc);
            } else if (MODE == 1) {
                int mxm = p.mx[m];
                float z = sgm(p.EX[(size_t)mxm * 768 + col] + acc);
                p.zu[(size_t)m * 256 + col] =
                    (unsigned short)__float2uint_rn(z * 65535.f);
            } else if (MODE == 2) {
                int mxm = p.mx[m];
                float z = (float)p.zu[(size_t)m * 256 + col] * (1.f / 65535.f);
                float sh = __bfloat162float(p.shh[(size_t)m * 256 + col])
                         + __bfloat162float(p.shl[(size_t)m * 256 + col]);
                float h = (1.f - z) * sh
                        + z * tanhf(p.EX[(size_t)mxm * 768 + 256 + col] + acc);
                if (m == 0) h = 0.f;
                __nv_bfloat16 hb = __float2bfloat16(h);
                p.rec[(size_t)m * 768 + col] = hb;
                p.rec[(size_t)m * 768 + 256 + col] =
                    __float2bfloat16(h - __bfloat162float(hb));
            } else {
                int fn = p.fn[m];
                p.nv[(size_t)m * 256 + col] =
                    fmaxf(p.EO[(size_t)fn * 256 + col] + acc, 0.f);
            }
        }
    }
#endif
}

// ---------------- orchestration --------------------------------------------
extern "C" void kernel_launch(void* const* d_in, const int* in_sizes, int n_in,
                              void* d_out, int out_size) {
    const int*   fnode = (const int*)d_in[0];
    const int*   fmess = (const int*)d_in[1];
    const int*   ng    = (const int*)d_in[2];
    const int*   mg    = (const int*)d_in[3];
    const int*   scope = (const int*)d_in[4];
    const float* emb   = (const float*)d_in[5];
    const float* Wz    = (const float*)d_in[6];
    const float* Wzb   = (const float*)d_in[7];
    const float* Wr    = (const float*)d_in[8];
    const float* Ur    = (const float*)d_in[9];
    const float* Urb   = (const float*)d_in[10];
    const float* Wh    = (const float*)d_in[11];
    const float* Whb   = (const float*)d_in[12];
    const float* Ow    = (const float*)d_in[13];
    const float* Ob    = (const float*)d_in[14];
    float* out = (float*)d_out;

    __nv_bfloat16 *rec, *shh, *shl, *sgh, *sgl, *mnh, *mnl;
    __nv_bfloat16 *BUh, *BUl, *BZh, *BZl, *BHh, *BHl, *BOh, *BOl;
    unsigned short* zu;
    float *nv, *EX, *EO;
    int* mx;
    cudaGetSymbolAddress((void**)&rec, g_rec);
    cudaGetSymbolAddress((void**)&shh, g_shh); cudaGetSymbolAddress((void**)&shl, g_shl);
    cudaGetSymbolAddress((void**)&sgh, g_sgh); cudaGetSymbolAddress((void**)&sgl, g_sgl);
    cudaGetSymbolAddress((void**)&mnh, g_mnh); cudaGetSymbolAddress((void**)&mnl, g_mnl);
    cudaGetSymbolAddress((void**)&zu,  g_zu);
    cudaGetSymbolAddress((void**)&nv,  g_nv);
    cudaGetSymbolAddress((void**)&EX,  g_EX);
    cudaGetSymbolAddress((void**)&EO,  g_EO);
    cudaGetSymbolAddress((void**)&mx,  g_mx);
    cudaGetSymbolAddress((void**)&BUh, g_BUh); cudaGetSymbolAddress((void**)&BUl, g_BUl);
    cudaGetSymbolAddress((void**)&BZh, g_BZh); cudaGetSymbolAddress((void**)&BZl, g_BZl);
    cudaGetSymbolAddress((void**)&BHh, g_BHh); cudaGetSymbolAddress((void**)&BHl, g_BHl);
    cudaGetSymbolAddress((void**)&BOh, g_BOh); cudaGetSymbolAddress((void**)&BOl, g_BOl);

    cudaFuncSetAttribute(tgemm<0>, cudaFuncAttributeMaxDynamicSharedMemorySize, TG_SMEM);
    cudaFuncSetAttribute(tgemm<1>, cudaFuncAttributeMaxDynamicSharedMemorySize, TG_SMEM);
    cudaFuncSetAttribute(tgemm<2>, cudaFuncAttributeMaxDynamicSharedMemorySize, TG_SMEM);
    cudaFuncSetAttribute(tgemm<3>, cudaFuncAttributeMaxDynamicSharedMemorySize, TG_SMEM);

    size_t recw = (size_t)M_MSG * 768 * 2 / 4;
    k_zero<<<(unsigned)((recw + 255) / 256), 256>>>((uint32_t*)rec, recw);
    k_pack<<<512, 256>>>(Wz, Wh, Ur, Ow, fnode, fmess, mx);
    k_prep<<<780, 256>>>(emb, Wz, Wh, Wr, Ow, Wzb, Whb, Urb, Ob, EX, EO);

    for (int d = 0; d < DEPTH; d++) {
        // U = h @ Ur  -> rec[:,512:768]
        TG pU{}; pU.Ah = rec; pU.Al = rec + 256; pU.lda = 768;
        pU.Bh = BUh; pU.Bl = BUl; pU.rec = rec; pU.mT = M_MSG / 128;
        tgemm<0><<<GRID_P, 256, TG_SMEM>>>(pU);
        // gather: sum_h, sum_gh — two column-half passes for L2 residency
        k_gather<<<(M_MSG * 32) / 256, 256>>>(mg, rec, EX, mx, shh, shl, sgh, sgl, 0);
        k_gather<<<(M_MSG * 32) / 256, 256>>>(mg, rec, EX, mx, shh, shl, sgh, sgl, 128);
        // z = sigmoid(EXz[mx] + sum_h @ Wzh)
        TG pZ{}; pZ.Ah = shh; pZ.Al = shl; pZ.lda = 256;
        pZ.Bh = BZh; pZ.Bl = BZl; pZ.zu = zu; pZ.EX = EX; pZ.mx = mx;
        pZ.mT = M_MSG / 128;
        tgemm<1><<<GRID_P, 256, TG_SMEM>>>(pZ);
        // h = (1-z)*sum_h + z*tanh(EXh[mx] + sum_gh @ Whh) -> rec h planes
        TG pH{}; pH.Ah = sgh; pH.Al = sgl; pH.lda = 256;
        pH.Bh = BHh; pH.Bl = BHl; pH.rec = rec; pH.zu = zu;
        pH.EX = EX; pH.mx = mx; pH.shh = shh; pH.shl = shl;
        pH.mT = M_MSG / 128;
        tgemm<2><<<GRID_P, 256, TG_SMEM>>>(pH);
    }

    // mess_nei per node
    k_gnode<<<(NNODE * 64) / 256, 256>>>(ng, rec, mnh, mnl);

    // node_vec = relu(EO[fnode] + mn @ Ow2)
    TG pN{}; pN.Ah = mnh; pN.Al = mnl; pN.lda = 256;
    pN.Bh = BOh; pN.Bl = BOl; pN.EO = EO; pN.fn = fnode; pN.nv = nv;
    pN.mT = NNODE / 128;
    tgemm<3><<<GRID_P, 256, TG_SMEM>>>(pN);

    // segment mean (sorted scopes, deterministic)
    k_seg<<<NTREE, 256>>>(scope, nv, out);
}